// round 2
// baseline (speedup 1.0000x reference)
#include <cuda_runtime.h>
#include <math.h>

#define BATCH 4
#define CC    256
#define CQ    32
#define NTOK  4096

// scratch (allocation-free rule: __device__ globals)
__device__ float g_q[BATCH * CQ * NTOK];
__device__ float g_k[BATCH * CQ * NTOK];
__device__ float g_v[BATCH * CC * NTOK];

// ---------- packed f32x2 helpers ----------
__device__ __forceinline__ unsigned long long pack2(float lo, float hi) {
    unsigned long long r;
    asm("mov.b64 %0, {%1,%2};" : "=l"(r) : "f"(lo), "f"(hi));
    return r;
}
__device__ __forceinline__ void unpack2(unsigned long long v, float& lo, float& hi) {
    asm("mov.b64 {%0,%1}, %2;" : "=f"(lo), "=f"(hi) : "l"(v));
}
__device__ __forceinline__ unsigned long long fma2(unsigned long long a,
                                                   unsigned long long b,
                                                   unsigned long long c) {
    unsigned long long d;
    asm("fma.rn.f32x2 %0, %1, %2, %3;" : "=l"(d) : "l"(a), "l"(b), "l"(c));
    return d;
}
__device__ __forceinline__ unsigned long long mul2(unsigned long long a,
                                                   unsigned long long b) {
    unsigned long long d;
    asm("mul.rn.f32x2 %0, %1, %2;" : "=l"(d) : "l"(a), "l"(b));
    return d;
}

// =====================================================================
// Kernel 1: 1x1-conv projections. out rows: [0,32)=q, [32,64)=k, [64,320)=v
// grid: (32 n-tiles of 128, 5 row-tiles of 64, 4 batches), 256 threads
// =====================================================================
__global__ __launch_bounds__(256) void proj_kernel(
    const float* __restrict__ x,
    const float* __restrict__ wq, const float* __restrict__ bq,
    const float* __restrict__ wk, const float* __restrict__ bk,
    const float* __restrict__ wv, const float* __restrict__ bv)
{
    __shared__ float sX[32 * 128];   // [c_local][n_local]
    __shared__ float sW[32 * 68];    // [c_local][r_local] padded

    const int n0 = blockIdx.x * 128;
    const int r0 = blockIdx.y * 64;
    const int b  = blockIdx.z;
    const int t  = threadIdx.x;
    const int rg = t >> 4;           // 0..15 -> rows 4*rg..4*rg+3
    const int ng = t & 15;           // 0..15 -> cols 4*ng.. and 64+4*ng..

    float acc[4][8];
#pragma unroll
    for (int j = 0; j < 4; j++)
#pragma unroll
        for (int i = 0; i < 8; i++) acc[j][i] = 0.0f;

    for (int cc = 0; cc < CC; cc += 32) {
        // load X tile [32][128]
#pragma unroll
        for (int p = 0; p < 4; p++) {
            int idx = p * 256 + t;               // 0..1023 float4s
            int cr = idx >> 5, l = idx & 31;
            float4 v = *(const float4*)(x + ((size_t)b * CC + cc + cr) * NTOK + n0 + 4 * l);
            *(float4*)(sX + cr * 128 + 4 * l) = v;
        }
        // load W tile transposed sW[c][r]
#pragma unroll
        for (int p = 0; p < 2; p++) {
            int idx = p * 256 + t;               // 0..511
            int rl = idx >> 3, cf = idx & 7;     // rl 0..63, cf 0..7
            int rglob = r0 + rl;
            const float* wrow;
            if (rglob < CQ)          wrow = wq + (size_t)rglob * CC;
            else if (rglob < 2 * CQ) wrow = wk + (size_t)(rglob - CQ) * CC;
            else                     wrow = wv + (size_t)(rglob - 2 * CQ) * CC;
            float4 v = *(const float4*)(wrow + cc + 4 * cf);
            sW[(4 * cf + 0) * 68 + rl] = v.x;
            sW[(4 * cf + 1) * 68 + rl] = v.y;
            sW[(4 * cf + 2) * 68 + rl] = v.z;
            sW[(4 * cf + 3) * 68 + rl] = v.w;
        }
        __syncthreads();

#pragma unroll
        for (int c = 0; c < 32; c++) {
            float4 w  = *(float4*)(sW + c * 68 + 4 * rg);
            float4 x1 = *(float4*)(sX + c * 128 + 4 * ng);
            float4 x2 = *(float4*)(sX + c * 128 + 64 + 4 * ng);
            float wj[4] = {w.x, w.y, w.z, w.w};
            float xs[8] = {x1.x, x1.y, x1.z, x1.w, x2.x, x2.y, x2.z, x2.w};
#pragma unroll
            for (int j = 0; j < 4; j++)
#pragma unroll
                for (int i = 0; i < 8; i++) acc[j][i] = fmaf(wj[j], xs[i], acc[j][i]);
        }
        __syncthreads();
    }

#pragma unroll
    for (int j = 0; j < 4; j++) {
        int rglob = r0 + 4 * rg + j;
        float bias;
        float* dst;
        if (rglob < CQ)          { bias = bq[rglob];          dst = g_q + ((size_t)b * CQ + rglob) * NTOK; }
        else if (rglob < 2 * CQ) { bias = bk[rglob - CQ];     dst = g_k + ((size_t)b * CQ + rglob - CQ) * NTOK; }
        else                     { bias = bv[rglob - 2 * CQ]; dst = g_v + ((size_t)b * CC + rglob - 2 * CQ) * NTOK; }
        float4 o1 = {acc[j][0] + bias, acc[j][1] + bias, acc[j][2] + bias, acc[j][3] + bias};
        float4 o2 = {acc[j][4] + bias, acc[j][5] + bias, acc[j][6] + bias, acc[j][7] + bias};
        *(float4*)(dst + n0 + 4 * ng)      = o1;
        *(float4*)(dst + n0 + 64 + 4 * ng) = o2;
    }
}

// =====================================================================
// Kernel 2: flash attention (fp32, packed f32x2 PV) + residual epilogue
// grid: 256 CTAs = 4 batches x 64 query-tiles(64), 256 threads
// thread (mg = t/16, ng = t%16): queries m = 4*mg+j, channels o = ng+16*i
// =====================================================================
#define SMEM_FLOATS (256 * 65 + 32 * 64 + 32 * 64 + 64 * 68)

__global__ __launch_bounds__(256, 2) void attn_kernel(
    const float* __restrict__ x,
    const float* __restrict__ gamma,
    float* __restrict__ out)
{
    extern __shared__ float sm[];
    float* sV  = sm;                       // [256][65]  padded V tile (o-major)
    float* sQ  = sm + 256 * 65;            // [32][64]   Q tile (c-major)
    float* sK  = sQ + 32 * 64;             // [32][64]   K tile (c-major)
    float* sPt = sK + 32 * 64;             // [64][68]   P transposed [n'][m]

    const int t  = threadIdx.x;
    const int mg = t >> 4;                 // 0..15
    const int ng = t & 15;                 // 0..15
    const int b  = blockIdx.x >> 6;
    const int q0 = (blockIdx.x & 63) * 64;

    const float* qb = g_q + (size_t)b * CQ * NTOK;
    const float* kb = g_k + (size_t)b * CQ * NTOK;
    const float* vb = g_v + (size_t)b * CC * NTOK;

    // load Q tile once: sQ[c][m]
#pragma unroll
    for (int p = 0; p < 2; p++) {
        int idx = p * 256 + t;             // 0..511 float4s
        int c = idx >> 4, l = idx & 15;
        float4 v = *(const float4*)(qb + (size_t)c * NTOK + q0 + 4 * l);
        *(float4*)(sQ + c * 64 + 4 * l) = v;
    }

    unsigned long long acc[2][16];         // [query-pair][channel], f32x2 packed
#pragma unroll
    for (int jp = 0; jp < 2; jp++)
#pragma unroll
        for (int i = 0; i < 16; i++) acc[jp][i] = 0ull;

    float run_m[4] = {-INFINITY, -INFINITY, -INFINITY, -INFINITY};
    float run_l[4] = {0.f, 0.f, 0.f, 0.f};

    for (int j0 = 0; j0 < NTOK; j0 += 64) {
        __syncthreads();   // previous PV finished reading sV/sPt
        // load K tile
#pragma unroll
        for (int p = 0; p < 2; p++) {
            int idx = p * 256 + t;
            int c = idx >> 4, l = idx & 15;
            float4 v = *(const float4*)(kb + (size_t)c * NTOK + j0 + 4 * l);
            *(float4*)(sK + c * 64 + 4 * l) = v;
        }
        // load V tile: sV[o][n'] stride 65 (conflict-free reads with o=ng+16i)
#pragma unroll
        for (int p = 0; p < 16; p++) {
            int idx = p * 256 + t;         // 0..4095 float4s
            int o = idx >> 4, l = idx & 15;
            float4 v = *(const float4*)(vb + (size_t)o * NTOK + j0 + 4 * l);
            float* d = sV + o * 65 + 4 * l;
            d[0] = v.x; d[1] = v.y; d[2] = v.z; d[3] = v.w;
        }
        __syncthreads();

        // ---- S = Q Kᵀ (fp32, exact scores) ----
        float s[4][4];
#pragma unroll
        for (int j = 0; j < 4; j++)
#pragma unroll
            for (int i = 0; i < 4; i++) s[j][i] = 0.0f;
#pragma unroll
        for (int c = 0; c < 32; c++) {
            float4 q = *(float4*)(sQ + c * 64 + 4 * mg);
            float4 k = *(float4*)(sK + c * 64 + 4 * ng);
            float qj[4] = {q.x, q.y, q.z, q.w};
            float ki[4] = {k.x, k.y, k.z, k.w};
#pragma unroll
            for (int j = 0; j < 4; j++)
#pragma unroll
                for (int i = 0; i < 4; i++) s[j][i] = fmaf(qj[j], ki[i], s[j][i]);
        }

        // ---- online softmax (shfl over the 16 ng lanes) ----
        float p[4][4], alpha[4];
#pragma unroll
        for (int j = 0; j < 4; j++) {
            float rm = fmaxf(fmaxf(s[j][0], s[j][1]), fmaxf(s[j][2], s[j][3]));
#pragma unroll
            for (int d = 1; d < 16; d <<= 1)
                rm = fmaxf(rm, __shfl_xor_sync(0xffffffffu, rm, d));
            float mnew = fmaxf(run_m[j], rm);
            alpha[j] = __expf(run_m[j] - mnew);
            float rs = 0.0f;
#pragma unroll
            for (int i = 0; i < 4; i++) {
                p[j][i] = __expf(s[j][i] - mnew);
                rs += p[j][i];
            }
#pragma unroll
            for (int d = 1; d < 16; d <<= 1)
                rs += __shfl_xor_sync(0xffffffffu, rs, d);
            run_l[j] = run_l[j] * alpha[j] + rs;
            run_m[j] = mnew;
        }

        // write P transposed: sPt[n'][m]
#pragma unroll
        for (int i = 0; i < 4; i++) {
            float4 v = {p[0][i], p[1][i], p[2][i], p[3][i]};
            *(float4*)(sPt + (4 * ng + i) * 68 + 4 * mg) = v;
        }

        // rescale accumulators by alpha (packed)
        unsigned long long a01 = pack2(alpha[0], alpha[1]);
        unsigned long long a23 = pack2(alpha[2], alpha[3]);
#pragma unroll
        for (int i = 0; i < 16; i++) {
            acc[0][i] = mul2(acc[0][i], a01);
            acc[1][i] = mul2(acc[1][i], a23);
        }
        __syncthreads();

        // ---- PV: acc[m][o] += sum_n' P[m][n'] * V[o][n'] (f32x2) ----
#pragma unroll 2
        for (int n = 0; n < 64; n++) {
            float4 pv = *(float4*)(sPt + n * 68 + 4 * mg);
            unsigned long long p01 = pack2(pv.x, pv.y);
            unsigned long long p23 = pack2(pv.z, pv.w);
#pragma unroll
            for (int i = 0; i < 16; i++) {
                float v = sV[(ng + 16 * i) * 65 + n];
                unsigned long long vv = pack2(v, v);
                acc[0][i] = fma2(p01, vv, acc[0][i]);
                acc[1][i] = fma2(p23, vv, acc[1][i]);
            }
        }
    }

    // ---- epilogue: out = gamma*acc/l + x ----
    float gm = gamma[0];
    float sc[4];
#pragma unroll
    for (int j = 0; j < 4; j++) sc[j] = gm / run_l[j];

    const float* xb = x   + (size_t)b * CC * NTOK;
    float*       ob = out + (size_t)b * CC * NTOK;
#pragma unroll
    for (int i = 0; i < 16; i++) {
        int o = ng + 16 * i;
        float a0, a1, a2, a3;
        unpack2(acc[0][i], a0, a1);
        unpack2(acc[1][i], a2, a3);
        size_t base = (size_t)o * NTOK + q0 + 4 * mg;
        float4 xv = *(const float4*)(xb + base);
        float4 r = {fmaf(sc[0], a0, xv.x), fmaf(sc[1], a1, xv.y),
                    fmaf(sc[2], a2, xv.z), fmaf(sc[3], a3, xv.w)};
        *(float4*)(ob + base) = r;
    }
}

// =====================================================================
extern "C" void kernel_launch(void* const* d_in, const int* in_sizes, int n_in,
                              void* d_out, int out_size)
{
    const float* x     = (const float*)d_in[0];
    const float* wq    = (const float*)d_in[1];
    const float* bq    = (const float*)d_in[2];
    const float* wk    = (const float*)d_in[3];
    const float* bk    = (const float*)d_in[4];
    const float* wv    = (const float*)d_in[5];
    const float* bv    = (const float*)d_in[6];
    const float* gamma = (const float*)d_in[7];
    float* out = (float*)d_out;

    dim3 pgrid(NTOK / 128, 5, BATCH);
    proj_kernel<<<pgrid, 256>>>(x, wq, bq, wk, bk, wv, bv);

    const int smem_bytes = SMEM_FLOATS * (int)sizeof(float);   // 100352
    cudaFuncSetAttribute(attn_kernel, cudaFuncAttributeMaxDynamicSharedMemorySize, smem_bytes);
    attn_kernel<<<BATCH * (NTOK / 64), 256, smem_bytes>>>(x, gamma, out);
}

// round 3
// speedup vs baseline: 1.0012x; 1.0012x over previous
#include <cuda_runtime.h>
#include <math.h>

#define BATCH 4
#define CC    256
#define CQ    32
#define NTOK  4096

// scratch (allocation-free rule: __device__ globals)
__device__ float g_q[BATCH * CQ * NTOK];
__device__ float g_k[BATCH * CQ * NTOK];
__device__ float g_v[BATCH * CC * NTOK];

// ---------- packed f32x2 helpers ----------
__device__ __forceinline__ unsigned long long pack2(float lo, float hi) {
    unsigned long long r;
    asm("mov.b64 %0, {%1,%2};" : "=l"(r) : "f"(lo), "f"(hi));
    return r;
}
__device__ __forceinline__ void unpack2(unsigned long long v, float& lo, float& hi) {
    asm("mov.b64 {%0,%1}, %2;" : "=f"(lo), "=f"(hi) : "l"(v));
}
__device__ __forceinline__ unsigned long long fma2(unsigned long long a,
                                                   unsigned long long b,
                                                   unsigned long long c) {
    unsigned long long d;
    asm("fma.rn.f32x2 %0, %1, %2, %3;" : "=l"(d) : "l"(a), "l"(b), "l"(c));
    return d;
}
__device__ __forceinline__ unsigned long long mul2(unsigned long long a,
                                                   unsigned long long b) {
    unsigned long long d;
    asm("mul.rn.f32x2 %0, %1, %2;" : "=l"(d) : "l"(a), "l"(b));
    return d;
}

// =====================================================================
// Kernel 1: 1x1-conv projections. out rows: [0,32)=q, [32,64)=k, [64,320)=v
// grid: (32 n-tiles of 128, 5 row-tiles of 64, 4 batches), 256 threads
// =====================================================================
__global__ __launch_bounds__(256) void proj_kernel(
    const float* __restrict__ x,
    const float* __restrict__ wq, const float* __restrict__ bq,
    const float* __restrict__ wk, const float* __restrict__ bk,
    const float* __restrict__ wv, const float* __restrict__ bv)
{
    __shared__ float sX[32 * 128];   // [c_local][n_local]
    __shared__ float sW[32 * 68];    // [c_local][r_local] padded

    const int n0 = blockIdx.x * 128;
    const int r0 = blockIdx.y * 64;
    const int b  = blockIdx.z;
    const int t  = threadIdx.x;
    const int rg = t >> 4;           // 0..15 -> rows 4*rg..4*rg+3
    const int ng = t & 15;           // 0..15 -> cols 4*ng.. and 64+4*ng..

    float acc[4][8];
#pragma unroll
    for (int j = 0; j < 4; j++)
#pragma unroll
        for (int i = 0; i < 8; i++) acc[j][i] = 0.0f;

    for (int cc = 0; cc < CC; cc += 32) {
        // load X tile [32][128]
#pragma unroll
        for (int p = 0; p < 4; p++) {
            int idx = p * 256 + t;               // 0..1023 float4s
            int cr = idx >> 5, l = idx & 31;
            float4 v = *(const float4*)(x + ((size_t)b * CC + cc + cr) * NTOK + n0 + 4 * l);
            *(float4*)(sX + cr * 128 + 4 * l) = v;
        }
        // load W tile transposed sW[c][r]
#pragma unroll
        for (int p = 0; p < 2; p++) {
            int idx = p * 256 + t;               // 0..511
            int rl = idx >> 3, cf = idx & 7;     // rl 0..63, cf 0..7
            int rglob = r0 + rl;
            const float* wrow;
            if (rglob < CQ)          wrow = wq + (size_t)rglob * CC;
            else if (rglob < 2 * CQ) wrow = wk + (size_t)(rglob - CQ) * CC;
            else                     wrow = wv + (size_t)(rglob - 2 * CQ) * CC;
            float4 v = *(const float4*)(wrow + cc + 4 * cf);
            sW[(4 * cf + 0) * 68 + rl] = v.x;
            sW[(4 * cf + 1) * 68 + rl] = v.y;
            sW[(4 * cf + 2) * 68 + rl] = v.z;
            sW[(4 * cf + 3) * 68 + rl] = v.w;
        }
        __syncthreads();

#pragma unroll
        for (int c = 0; c < 32; c++) {
            float4 w  = *(float4*)(sW + c * 68 + 4 * rg);
            float4 x1 = *(float4*)(sX + c * 128 + 4 * ng);
            float4 x2 = *(float4*)(sX + c * 128 + 64 + 4 * ng);
            float wj[4] = {w.x, w.y, w.z, w.w};
            float xs[8] = {x1.x, x1.y, x1.z, x1.w, x2.x, x2.y, x2.z, x2.w};
#pragma unroll
            for (int j = 0; j < 4; j++)
#pragma unroll
                for (int i = 0; i < 8; i++) acc[j][i] = fmaf(wj[j], xs[i], acc[j][i]);
        }
        __syncthreads();
    }

#pragma unroll
    for (int j = 0; j < 4; j++) {
        int rglob = r0 + 4 * rg + j;
        float bias;
        float* dst;
        if (rglob < CQ)          { bias = bq[rglob];          dst = g_q + ((size_t)b * CQ + rglob) * NTOK; }
        else if (rglob < 2 * CQ) { bias = bk[rglob - CQ];     dst = g_k + ((size_t)b * CQ + rglob - CQ) * NTOK; }
        else                     { bias = bv[rglob - 2 * CQ]; dst = g_v + ((size_t)b * CC + rglob - 2 * CQ) * NTOK; }
        float4 o1 = {acc[j][0] + bias, acc[j][1] + bias, acc[j][2] + bias, acc[j][3] + bias};
        float4 o2 = {acc[j][4] + bias, acc[j][5] + bias, acc[j][6] + bias, acc[j][7] + bias};
        *(float4*)(dst + n0 + 4 * ng)      = o1;
        *(float4*)(dst + n0 + 64 + 4 * ng) = o2;
    }
}

// =====================================================================
// Kernel 2: flash attention (fp32, packed f32x2 PV) + residual epilogue
// grid: 256 CTAs = 4 batches x 64 query-tiles(64), 256 threads
// thread (mg = t/16, ng = t%16): queries m = 4*mg+j, channels o = ng+16*i
// =====================================================================
#define SMEM_FLOATS (256 * 65 + 32 * 64 + 32 * 64 + 64 * 68)

__global__ __launch_bounds__(256, 2) void attn_kernel(
    const float* __restrict__ x,
    const float* __restrict__ gamma,
    float* __restrict__ out)
{
    extern __shared__ float sm[];
    float* sV  = sm;                       // [256][65]  padded V tile (o-major)
    float* sQ  = sm + 256 * 65;            // [32][64]   Q tile (c-major)
    float* sK  = sQ + 32 * 64;             // [32][64]   K tile (c-major)
    float* sPt = sK + 32 * 64;             // [64][68]   P transposed [n'][m]

    const int t  = threadIdx.x;
    const int mg = t >> 4;                 // 0..15
    const int ng = t & 15;                 // 0..15
    const int b  = blockIdx.x >> 6;
    const int q0 = (blockIdx.x & 63) * 64;

    const float* qb = g_q + (size_t)b * CQ * NTOK;
    const float* kb = g_k + (size_t)b * CQ * NTOK;
    const float* vb = g_v + (size_t)b * CC * NTOK;

    // load Q tile once: sQ[c][m]
#pragma unroll
    for (int p = 0; p < 2; p++) {
        int idx = p * 256 + t;             // 0..511 float4s
        int c = idx >> 4, l = idx & 15;
        float4 v = *(const float4*)(qb + (size_t)c * NTOK + q0 + 4 * l);
        *(float4*)(sQ + c * 64 + 4 * l) = v;
    }

    unsigned long long acc[2][16];         // [query-pair][channel], f32x2 packed
#pragma unroll
    for (int jp = 0; jp < 2; jp++)
#pragma unroll
        for (int i = 0; i < 16; i++) acc[jp][i] = 0ull;

    float run_m[4] = {-INFINITY, -INFINITY, -INFINITY, -INFINITY};
    float run_l[4] = {0.f, 0.f, 0.f, 0.f};

    for (int j0 = 0; j0 < NTOK; j0 += 64) {
        __syncthreads();   // previous PV finished reading sV/sPt
        // load K tile
#pragma unroll
        for (int p = 0; p < 2; p++) {
            int idx = p * 256 + t;
            int c = idx >> 4, l = idx & 15;
            float4 v = *(const float4*)(kb + (size_t)c * NTOK + j0 + 4 * l);
            *(float4*)(sK + c * 64 + 4 * l) = v;
        }
        // load V tile: sV[o][n'] stride 65 (conflict-free reads with o=ng+16i)
#pragma unroll
        for (int p = 0; p < 16; p++) {
            int idx = p * 256 + t;         // 0..4095 float4s
            int o = idx >> 4, l = idx & 15;
            float4 v = *(const float4*)(vb + (size_t)o * NTOK + j0 + 4 * l);
            float* d = sV + o * 65 + 4 * l;
            d[0] = v.x; d[1] = v.y; d[2] = v.z; d[3] = v.w;
        }
        __syncthreads();

        // ---- S = Q Kᵀ (fp32, exact scores) ----
        float s[4][4];
#pragma unroll
        for (int j = 0; j < 4; j++)
#pragma unroll
            for (int i = 0; i < 4; i++) s[j][i] = 0.0f;
#pragma unroll
        for (int c = 0; c < 32; c++) {
            float4 q = *(float4*)(sQ + c * 64 + 4 * mg);
            float4 k = *(float4*)(sK + c * 64 + 4 * ng);
            float qj[4] = {q.x, q.y, q.z, q.w};
            float ki[4] = {k.x, k.y, k.z, k.w};
#pragma unroll
            for (int j = 0; j < 4; j++)
#pragma unroll
                for (int i = 0; i < 4; i++) s[j][i] = fmaf(qj[j], ki[i], s[j][i]);
        }

        // ---- online softmax (shfl over the 16 ng lanes) ----
        float p[4][4], alpha[4];
#pragma unroll
        for (int j = 0; j < 4; j++) {
            float rm = fmaxf(fmaxf(s[j][0], s[j][1]), fmaxf(s[j][2], s[j][3]));
#pragma unroll
            for (int d = 1; d < 16; d <<= 1)
                rm = fmaxf(rm, __shfl_xor_sync(0xffffffffu, rm, d));
            float mnew = fmaxf(run_m[j], rm);
            alpha[j] = __expf(run_m[j] - mnew);
            float rs = 0.0f;
#pragma unroll
            for (int i = 0; i < 4; i++) {
                p[j][i] = __expf(s[j][i] - mnew);
                rs += p[j][i];
            }
#pragma unroll
            for (int d = 1; d < 16; d <<= 1)
                rs += __shfl_xor_sync(0xffffffffu, rs, d);
            run_l[j] = run_l[j] * alpha[j] + rs;
            run_m[j] = mnew;
        }

        // write P transposed: sPt[n'][m]
#pragma unroll
        for (int i = 0; i < 4; i++) {
            float4 v = {p[0][i], p[1][i], p[2][i], p[3][i]};
            *(float4*)(sPt + (4 * ng + i) * 68 + 4 * mg) = v;
        }

        // rescale accumulators by alpha (packed)
        unsigned long long a01 = pack2(alpha[0], alpha[1]);
        unsigned long long a23 = pack2(alpha[2], alpha[3]);
#pragma unroll
        for (int i = 0; i < 16; i++) {
            acc[0][i] = mul2(acc[0][i], a01);
            acc[1][i] = mul2(acc[1][i], a23);
        }
        __syncthreads();

        // ---- PV: acc[m][o] += sum_n' P[m][n'] * V[o][n'] (f32x2) ----
#pragma unroll 2
        for (int n = 0; n < 64; n++) {
            float4 pv = *(float4*)(sPt + n * 68 + 4 * mg);
            unsigned long long p01 = pack2(pv.x, pv.y);
            unsigned long long p23 = pack2(pv.z, pv.w);
#pragma unroll
            for (int i = 0; i < 16; i++) {
                float v = sV[(ng + 16 * i) * 65 + n];
                unsigned long long vv = pack2(v, v);
                acc[0][i] = fma2(p01, vv, acc[0][i]);
                acc[1][i] = fma2(p23, vv, acc[1][i]);
            }
        }
    }

    // ---- epilogue: out = gamma*acc/l + x ----
    float gm = gamma[0];
    float sc[4];
#pragma unroll
    for (int j = 0; j < 4; j++) sc[j] = gm / run_l[j];

    const float* xb = x   + (size_t)b * CC * NTOK;
    float*       ob = out + (size_t)b * CC * NTOK;
#pragma unroll
    for (int i = 0; i < 16; i++) {
        int o = ng + 16 * i;
        float a0, a1, a2, a3;
        unpack2(acc[0][i], a0, a1);
        unpack2(acc[1][i], a2, a3);
        size_t base = (size_t)o * NTOK + q0 + 4 * mg;
        float4 xv = *(const float4*)(xb + base);
        float4 r = {fmaf(sc[0], a0, xv.x), fmaf(sc[1], a1, xv.y),
                    fmaf(sc[2], a2, xv.z), fmaf(sc[3], a3, xv.w)};
        *(float4*)(ob + base) = r;
    }
}

// =====================================================================
extern "C" void kernel_launch(void* const* d_in, const int* in_sizes, int n_in,
                              void* d_out, int out_size)
{
    const float* x     = (const float*)d_in[0];
    const float* wq    = (const float*)d_in[1];
    const float* bq    = (const float*)d_in[2];
    const float* wk    = (const float*)d_in[3];
    const float* bk    = (const float*)d_in[4];
    const float* wv    = (const float*)d_in[5];
    const float* bv    = (const float*)d_in[6];
    const float* gamma = (const float*)d_in[7];
    float* out = (float*)d_out;

    dim3 pgrid(NTOK / 128, 5, BATCH);
    proj_kernel<<<pgrid, 256>>>(x, wq, bq, wk, bk, wv, bv);

    const int smem_bytes = SMEM_FLOATS * (int)sizeof(float);   // 100352
    cudaFuncSetAttribute(attn_kernel, cudaFuncAttributeMaxDynamicSharedMemorySize, smem_bytes);
    attn_kernel<<<BATCH * (NTOK / 64), 256, smem_bytes>>>(x, gamma, out);
}

// round 5
// speedup vs baseline: 1.1262x; 1.1248x over previous
#include <cuda_runtime.h>
#include <math.h>

#define BATCH 4
#define CC    256
#define CQ    32
#define NTOK  4096

__device__ float g_q[BATCH * CQ * NTOK];
__device__ float g_k[BATCH * CQ * NTOK];
__device__ float g_v[BATCH * CC * NTOK];     // [b][o][n]
__device__ float g_vt[BATCH * NTOK * CC];    // [b][n][o]

typedef unsigned long long ull;
__device__ __forceinline__ ull pack2(float lo, float hi) {
    ull r; asm("mov.b64 %0, {%1,%2};" : "=l"(r) : "f"(lo), "f"(hi)); return r;
}
__device__ __forceinline__ void unpack2(ull v, float& lo, float& hi) {
    asm("mov.b64 {%0,%1}, %2;" : "=f"(lo), "=f"(hi) : "l"(v));
}
__device__ __forceinline__ ull fma2(ull a, ull b, ull c) {
    ull d; asm("fma.rn.f32x2 %0, %1, %2, %3;" : "=l"(d) : "l"(a), "l"(b), "l"(c)); return d;
}
__device__ __forceinline__ ull mul2(ull a, ull b) {
    ull d; asm("mul.rn.f32x2 %0, %1, %2;" : "=l"(d) : "l"(a), "l"(b)); return d;
}

// ============ Kernel 1: projections ============
__global__ __launch_bounds__(256) void proj_kernel(
    const float* __restrict__ x,
    const float* __restrict__ wq, const float* __restrict__ bq,
    const float* __restrict__ wk, const float* __restrict__ bk,
    const float* __restrict__ wv, const float* __restrict__ bv)
{
    __shared__ float sX[32 * 128];
    __shared__ float sW[32 * 68];
    const int n0 = blockIdx.x * 128, r0 = blockIdx.y * 64, b = blockIdx.z;
    const int t = threadIdx.x, rg = t >> 4, ng = t & 15;

    float acc[4][8];
#pragma unroll
    for (int j = 0; j < 4; j++)
#pragma unroll
        for (int i = 0; i < 8; i++) acc[j][i] = 0.0f;

    for (int cc = 0; cc < CC; cc += 32) {
#pragma unroll
        for (int p = 0; p < 4; p++) {
            int idx = p * 256 + t, cr = idx >> 5, l = idx & 31;
            float4 v = *(const float4*)(x + ((size_t)b * CC + cc + cr) * NTOK + n0 + 4 * l);
            *(float4*)(sX + cr * 128 + 4 * l) = v;
        }
#pragma unroll
        for (int p = 0; p < 2; p++) {
            int idx = p * 256 + t, rl = idx >> 3, cf = idx & 7;
            int rglob = r0 + rl;
            const float* wrow;
            if (rglob < CQ)          wrow = wq + (size_t)rglob * CC;
            else if (rglob < 2 * CQ) wrow = wk + (size_t)(rglob - CQ) * CC;
            else                     wrow = wv + (size_t)(rglob - 2 * CQ) * CC;
            float4 v = *(const float4*)(wrow + cc + 4 * cf);
            sW[(4 * cf + 0) * 68 + rl] = v.x;
            sW[(4 * cf + 1) * 68 + rl] = v.y;
            sW[(4 * cf + 2) * 68 + rl] = v.z;
            sW[(4 * cf + 3) * 68 + rl] = v.w;
        }
        __syncthreads();
#pragma unroll
        for (int c = 0; c < 32; c++) {
            float4 w  = *(float4*)(sW + c * 68 + 4 * rg);
            float4 x1 = *(float4*)(sX + c * 128 + 4 * ng);
            float4 x2 = *(float4*)(sX + c * 128 + 64 + 4 * ng);
            float wj[4] = {w.x, w.y, w.z, w.w};
            float xs[8] = {x1.x, x1.y, x1.z, x1.w, x2.x, x2.y, x2.z, x2.w};
#pragma unroll
            for (int j = 0; j < 4; j++)
#pragma unroll
                for (int i = 0; i < 8; i++) acc[j][i] = fmaf(wj[j], xs[i], acc[j][i]);
        }
        __syncthreads();
    }
#pragma unroll
    for (int j = 0; j < 4; j++) {
        int rglob = r0 + 4 * rg + j;
        float bias; float* dst;
        if (rglob < CQ)          { bias = bq[rglob];          dst = g_q + ((size_t)b * CQ + rglob) * NTOK; }
        else if (rglob < 2 * CQ) { bias = bk[rglob - CQ];     dst = g_k + ((size_t)b * CQ + rglob - CQ) * NTOK; }
        else                     { bias = bv[rglob - 2 * CQ]; dst = g_v + ((size_t)b * CC + rglob - 2 * CQ) * NTOK; }
        float4 o1 = {acc[j][0] + bias, acc[j][1] + bias, acc[j][2] + bias, acc[j][3] + bias};
        float4 o2 = {acc[j][4] + bias, acc[j][5] + bias, acc[j][6] + bias, acc[j][7] + bias};
        *(float4*)(dst + n0 + 4 * ng)      = o1;
        *(float4*)(dst + n0 + 64 + 4 * ng) = o2;
    }
}

// ============ Kernel 1b: V transpose [b][o][n] -> [b][n][o] ============
__global__ __launch_bounds__(256) void vt_kernel()
{
    __shared__ float sT[64 * 65];
    const int n0 = blockIdx.x * 64, o0 = blockIdx.y * 64, b = blockIdx.z;
    const int t = threadIdx.x;
    const float* src = g_v  + (size_t)b * CC * NTOK;
    float*       dst = g_vt + (size_t)b * NTOK * CC;
#pragma unroll
    for (int p = 0; p < 4; p++) {
        int idx = p * 256 + t, o = idx >> 4, k = idx & 15;
        float4 v = *(const float4*)(src + (size_t)(o0 + o) * NTOK + n0 + 4 * k);
        sT[o * 65 + 4 * k + 0] = v.x; sT[o * 65 + 4 * k + 1] = v.y;
        sT[o * 65 + 4 * k + 2] = v.z; sT[o * 65 + 4 * k + 3] = v.w;
    }
    __syncthreads();
#pragma unroll
    for (int p = 0; p < 4; p++) {
        int idx = p * 256 + t, n = idx >> 4, k = idx & 15;
        float4 w = {sT[(4 * k + 0) * 65 + n], sT[(4 * k + 1) * 65 + n],
                    sT[(4 * k + 2) * 65 + n], sT[(4 * k + 3) * 65 + n]};
        *(float4*)(dst + (size_t)(n0 + n) * CC + o0 + 4 * k) = w;
    }
}

// ============ Kernel 2: flash attention, packed inner loops ============
// smem floats: sV[64][256]=16384 | sQ[32][64]=2048 | sK=2048 | sPt[64][68]=4352 | sA[64]
#define SMEM_FLOATS (16384 + 2048 + 2048 + 4352 + 64)

__global__ __launch_bounds__(256, 2) void attn_kernel(
    const float* __restrict__ x,
    const float* __restrict__ gamma,
    float* __restrict__ out)
{
    extern __shared__ float sm[];
    float* sV  = sm;
    float* sQ  = sm + 16384;
    float* sK  = sQ + 2048;
    float* sPt = sK + 2048;
    float* sA  = sPt + 64 * 68;

    const int t = threadIdx.x;
    const int mg = t >> 4, ngs = t & 15;          // softmax map: m=4mg+j, n=4ngs+i
    const int w = t >> 5, lane = t & 31;          // PV map
    const int mg2 = lane >> 3, ng2 = lane & 7;
    const int m_base = 32 * (w & 1) + 8 * mg2;    // 8 consecutive m
    const int o_base = 64 * (w >> 1) + 4 * ng2;   // o = o_base + 32i + {0..3}
    const int b = blockIdx.x >> 6, q0 = (blockIdx.x & 63) * 64;

    const float* qb = g_q  + (size_t)b * CQ * NTOK;
    const float* kb = g_k  + (size_t)b * CQ * NTOK;
    const float* vb = g_vt + (size_t)b * NTOK * CC;

#pragma unroll
    for (int p = 0; p < 2; p++) {
        int idx = p * 256 + t, c = idx >> 4, l = idx & 15;
        *(float4*)(sQ + c * 64 + 4 * l) = *(const float4*)(qb + (size_t)c * NTOK + q0 + 4 * l);
    }

    ull acc[8][4];
#pragma unroll
    for (int j = 0; j < 8; j++)
#pragma unroll
        for (int k = 0; k < 4; k++) acc[j][k] = 0ull;
    float run_m[4] = {-INFINITY, -INFINITY, -INFINITY, -INFINITY};
    float run_l[4] = {0.f, 0.f, 0.f, 0.f};

    for (int j0 = 0; j0 < NTOK; j0 += 64) {
        __syncthreads();
#pragma unroll
        for (int p = 0; p < 2; p++) {   // K tile [32 c][64 n]
            int idx = p * 256 + t, c = idx >> 4, l = idx & 15;
            *(float4*)(sK + c * 64 + 4 * l) = *(const float4*)(kb + (size_t)c * NTOK + j0 + 4 * l);
        }
#pragma unroll
        for (int p = 0; p < 16; p++) {  // V tile [64 n][256 o]
            int idx = p * 256 + t, n = idx >> 6, c4 = idx & 63;
            *(float4*)(sV + n * 256 + 4 * c4) =
                *(const float4*)(vb + (size_t)(j0 + n) * CC + 4 * c4);
        }
        __syncthreads();

        // S = Q K^T, packed over key pairs
        ull s2[4][2];
#pragma unroll
        for (int j = 0; j < 4; j++) { s2[j][0] = 0ull; s2[j][1] = 0ull; }
#pragma unroll
        for (int c = 0; c < 32; c++) {
            float4 q = *(float4*)(sQ + c * 64 + 4 * mg);
            ulonglong2 k2 = *(ulonglong2*)(sK + c * 64 + 4 * ngs);
            float qj[4] = {q.x, q.y, q.z, q.w};
#pragma unroll
            for (int j = 0; j < 4; j++) {
                ull qd = pack2(qj[j], qj[j]);
                s2[j][0] = fma2(qd, k2.x, s2[j][0]);
                s2[j][1] = fma2(qd, k2.y, s2[j][1]);
            }
        }
        float s[4][4];
#pragma unroll
        for (int j = 0; j < 4; j++) {
            unpack2(s2[j][0], s[j][0], s[j][1]);
            unpack2(s2[j][1], s[j][2], s[j][3]);
        }

        // online softmax (reduce over 16 ngs lanes)
        float p[4][4], alpha[4];
#pragma unroll
        for (int j = 0; j < 4; j++) {
            float rm = fmaxf(fmaxf(s[j][0], s[j][1]), fmaxf(s[j][2], s[j][3]));
#pragma unroll
            for (int d = 1; d < 16; d <<= 1)
                rm = fmaxf(rm, __shfl_xor_sync(0xffffffffu, rm, d));
            float mnew = fmaxf(run_m[j], rm);
            alpha[j] = __expf(run_m[j] - mnew);
            float rs = 0.0f;
#pragma unroll
            for (int i = 0; i < 4; i++) { p[j][i] = __expf(s[j][i] - mnew); rs += p[j][i]; }
#pragma unroll
            for (int d = 1; d < 16; d <<= 1)
                rs += __shfl_xor_sync(0xffffffffu, rs, d);
            run_l[j] = run_l[j] * alpha[j] + rs;
            run_m[j] = mnew;
        }
#pragma unroll
        for (int i = 0; i < 4; i++) {   // P transposed [n][m]
            float4 v = {p[0][i], p[1][i], p[2][i], p[3][i]};
            *(float4*)(sPt + (4 * ngs + i) * 68 + 4 * mg) = v;
        }
        if (ngs == 0) {
#pragma unroll
            for (int j = 0; j < 4; j++) sA[4 * mg + j] = alpha[j];
        }
        __syncthreads();

        // rescale acc by alpha (per-m, packed dup)
        float4 a0 = *(float4*)(sA + m_base);
        float4 a1 = *(float4*)(sA + m_base + 4);
        float aj[8] = {a0.x, a0.y, a0.z, a0.w, a1.x, a1.y, a1.z, a1.w};
#pragma unroll
        for (int j = 0; j < 8; j++) {
            ull ad = pack2(aj[j], aj[j]);
#pragma unroll
            for (int k = 0; k < 4; k++) acc[j][k] = mul2(acc[j][k], ad);
        }

        // PV: 4 LDS + 8 mov + 32 FMA2 per n
#pragma unroll 2
        for (int n = 0; n < 64; n++) {
            ulonglong2 v0 = *(ulonglong2*)(sV + n * 256 + o_base);
            ulonglong2 v1 = *(ulonglong2*)(sV + n * 256 + o_base + 32);
            float4 p0 = *(float4*)(sPt + n * 68 + m_base);
            float4 p1 = *(float4*)(sPt + n * 68 + m_base + 4);
            float pj[8] = {p0.x, p0.y, p0.z, p0.w, p1.x, p1.y, p1.z, p1.w};
#pragma unroll
            for (int j = 0; j < 8; j++) {
                ull pd = pack2(pj[j], pj[j]);
                acc[j][0] = fma2(pd, v0.x, acc[j][0]);
                acc[j][1] = fma2(pd, v0.y, acc[j][1]);
                acc[j][2] = fma2(pd, v1.x, acc[j][2]);
                acc[j][3] = fma2(pd, v1.y, acc[j][3]);
            }
        }
    }

    // epilogue: out[o][q0+m] = gamma*acc/l + x
    __syncthreads();
    if (ngs == 0) {
        float gm = gamma[0];
#pragma unroll
        for (int j = 0; j < 4; j++) sA[4 * mg + j] = gm / run_l[j];
    }
    __syncthreads();
    float4 c0 = *(float4*)(sA + m_base);
    float4 c1 = *(float4*)(sA + m_base + 4);
    float sc[8] = {c0.x, c0.y, c0.z, c0.w, c1.x, c1.y, c1.z, c1.w};

    const float* xb = x   + (size_t)b * CC * NTOK;
    float*       ob = out + (size_t)b * CC * NTOK;
#pragma unroll
    for (int k = 0; k < 4; k++) {
        float lo[8], hi[8];
#pragma unroll
        for (int j = 0; j < 8; j++) unpack2(acc[j][k], lo[j], hi[j]);
        int o_lo = o_base + 32 * (k >> 1) + 2 * (k & 1);
#pragma unroll
        for (int hh = 0; hh < 2; hh++) {
            float* vals = hh ? hi : lo;
            size_t base = (size_t)(o_lo + hh) * NTOK + q0 + m_base;
            float4 x0 = *(const float4*)(xb + base);
            float4 x1 = *(const float4*)(xb + base + 4);
            float4 r0 = {fmaf(sc[0], vals[0], x0.x), fmaf(sc[1], vals[1], x0.y),
                         fmaf(sc[2], vals[2], x0.z), fmaf(sc[3], vals[3], x0.w)};
            float4 r1 = {fmaf(sc[4], vals[4], x1.x), fmaf(sc[5], vals[5], x1.y),
                         fmaf(sc[6], vals[6], x1.z), fmaf(sc[7], vals[7], x1.w)};
            *(float4*)(ob + base)     = r0;
            *(float4*)(ob + base + 4) = r1;
        }
    }
}

// ============ launch ============
extern "C" void kernel_launch(void* const* d_in, const int* in_sizes, int n_in,
                              void* d_out, int out_size)
{
    const float* x     = (const float*)d_in[0];
    const float* wq    = (const float*)d_in[1];
    const float* bq    = (const float*)d_in[2];
    const float* wk    = (const float*)d_in[3];
    const float* bk    = (const float*)d_in[4];
    const float* wv    = (const float*)d_in[5];
    const float* bv    = (const float*)d_in[6];
    const float* gamma = (const float*)d_in[7];
    float* out = (float*)d_out;

    dim3 pgrid(NTOK / 128, 5, BATCH);
    proj_kernel<<<pgrid, 256>>>(x, wq, bq, wk, bk, wv, bv);

    dim3 tgrid(NTOK / 64, CC / 64, BATCH);
    vt_kernel<<<tgrid, 256>>>();

    const int smem_bytes = SMEM_FLOATS * (int)sizeof(float);
    cudaFuncSetAttribute(attn_kernel, cudaFuncAttributeMaxDynamicSharedMemorySize, smem_bytes);
    attn_kernel<<<BATCH * (NTOK / 64), 256, smem_bytes>>>(x, gamma, out);
}

// round 6
// speedup vs baseline: 2.5834x; 2.2938x over previous
#include <cuda_runtime.h>
#include <math.h>

#define BATCH 4
#define CC    256
#define CQ    32
#define NTOK  4096

__device__ float g_q[BATCH * CQ * NTOK];
__device__ float g_k[BATCH * CQ * NTOK];
__device__ float g_v[BATCH * CC * NTOK];
__device__ float g_qh[BATCH * NTOK * CQ];
__device__ float g_ql[BATCH * NTOK * CQ];
__device__ float g_kh[BATCH * NTOK * CQ];
__device__ float g_kl[BATCH * NTOK * CQ];
__device__ float g_vt[BATCH * NTOK * CC];

__device__ __forceinline__ float tf32r(float v) {
    unsigned r; asm("cvt.rna.tf32.f32 %0, %1;" : "=r"(r) : "f"(v));
    return __uint_as_float(r);
}
__device__ __forceinline__ void mma8(float4& d, const unsigned* a, unsigned b0, unsigned b1) {
    asm volatile(
        "mma.sync.aligned.m16n8k8.row.col.f32.tf32.tf32.f32 "
        "{%0,%1,%2,%3},{%4,%5,%6,%7},{%8,%9},{%0,%1,%2,%3};"
        : "+f"(d.x), "+f"(d.y), "+f"(d.z), "+f"(d.w)
        : "r"(a[0]), "r"(a[1]), "r"(a[2]), "r"(a[3]), "r"(b0), "r"(b1));
}

// ============ Kernel 1: projections (unchanged) ============
__global__ __launch_bounds__(256) void proj_kernel(
    const float* __restrict__ x,
    const float* __restrict__ wq, const float* __restrict__ bq,
    const float* __restrict__ wk, const float* __restrict__ bk,
    const float* __restrict__ wv, const float* __restrict__ bv)
{
    __shared__ float sX[32 * 128];
    __shared__ float sW[32 * 68];
    const int n0 = blockIdx.x * 128, r0 = blockIdx.y * 64, b = blockIdx.z;
    const int t = threadIdx.x, rg = t >> 4, ng = t & 15;
    float acc[4][8];
#pragma unroll
    for (int j = 0; j < 4; j++)
#pragma unroll
        for (int i = 0; i < 8; i++) acc[j][i] = 0.0f;
    for (int cc = 0; cc < CC; cc += 32) {
#pragma unroll
        for (int p = 0; p < 4; p++) {
            int idx = p * 256 + t, cr = idx >> 5, l = idx & 31;
            float4 v = *(const float4*)(x + ((size_t)b * CC + cc + cr) * NTOK + n0 + 4 * l);
            *(float4*)(sX + cr * 128 + 4 * l) = v;
        }
#pragma unroll
        for (int p = 0; p < 2; p++) {
            int idx = p * 256 + t, rl = idx >> 3, cf = idx & 7;
            int rglob = r0 + rl;
            const float* wrow;
            if (rglob < CQ)          wrow = wq + (size_t)rglob * CC;
            else if (rglob < 2 * CQ) wrow = wk + (size_t)(rglob - CQ) * CC;
            else                     wrow = wv + (size_t)(rglob - 2 * CQ) * CC;
            float4 v = *(const float4*)(wrow + cc + 4 * cf);
            sW[(4 * cf + 0) * 68 + rl] = v.x;
            sW[(4 * cf + 1) * 68 + rl] = v.y;
            sW[(4 * cf + 2) * 68 + rl] = v.z;
            sW[(4 * cf + 3) * 68 + rl] = v.w;
        }
        __syncthreads();
#pragma unroll
        for (int c = 0; c < 32; c++) {
            float4 w  = *(float4*)(sW + c * 68 + 4 * rg);
            float4 x1 = *(float4*)(sX + c * 128 + 4 * ng);
            float4 x2 = *(float4*)(sX + c * 128 + 64 + 4 * ng);
            float wj[4] = {w.x, w.y, w.z, w.w};
            float xs[8] = {x1.x, x1.y, x1.z, x1.w, x2.x, x2.y, x2.z, x2.w};
#pragma unroll
            for (int j = 0; j < 4; j++)
#pragma unroll
                for (int i = 0; i < 8; i++) acc[j][i] = fmaf(wj[j], xs[i], acc[j][i]);
        }
        __syncthreads();
    }
#pragma unroll
    for (int j = 0; j < 4; j++) {
        int rglob = r0 + 4 * rg + j;
        float bias; float* dst;
        if (rglob < CQ)          { bias = bq[rglob];          dst = g_q + ((size_t)b * CQ + rglob) * NTOK; }
        else if (rglob < 2 * CQ) { bias = bk[rglob - CQ];     dst = g_k + ((size_t)b * CQ + rglob - CQ) * NTOK; }
        else                     { bias = bv[rglob - 2 * CQ]; dst = g_v + ((size_t)b * CC + rglob - 2 * CQ) * NTOK; }
        float4 o1 = {acc[j][0] + bias, acc[j][1] + bias, acc[j][2] + bias, acc[j][3] + bias};
        float4 o2 = {acc[j][4] + bias, acc[j][5] + bias, acc[j][6] + bias, acc[j][7] + bias};
        *(float4*)(dst + n0 + 4 * ng)      = o1;
        *(float4*)(dst + n0 + 64 + 4 * ng) = o2;
    }
}

// ============ Kernel 1b: q/k transpose + tf32 hi/lo split ============
__global__ __launch_bounds__(256) void tqk_kernel()
{
    __shared__ float sq[32 * 65], sk[32 * 65];
    const int n0 = blockIdx.x * 64, b = blockIdx.y, t = threadIdx.x;
    const float* qs = g_q + (size_t)b * CQ * NTOK;
    const float* ks = g_k + (size_t)b * CQ * NTOK;
#pragma unroll
    for (int p = 0; p < 2; p++) {
        int idx = p * 256 + t, c = idx >> 4, l = idx & 15;
        float4 vq = *(const float4*)(qs + (size_t)c * NTOK + n0 + 4 * l);
        float4 vk = *(const float4*)(ks + (size_t)c * NTOK + n0 + 4 * l);
        sq[c * 65 + 4 * l] = vq.x; sq[c * 65 + 4 * l + 1] = vq.y;
        sq[c * 65 + 4 * l + 2] = vq.z; sq[c * 65 + 4 * l + 3] = vq.w;
        sk[c * 65 + 4 * l] = vk.x; sk[c * 65 + 4 * l + 1] = vk.y;
        sk[c * 65 + 4 * l + 2] = vk.z; sk[c * 65 + 4 * l + 3] = vk.w;
    }
    __syncthreads();
    size_t ob = ((size_t)b * NTOK + n0) * CQ;
#pragma unroll
    for (int p = 0; p < 2; p++) {
        int idx = p * 256 + t, n = idx >> 3, cf = idx & 7;
        float4 qh, ql, kh, kl;
#pragma unroll
        for (int i = 0; i < 4; i++) {
            float v = sq[(4 * cf + i) * 65 + n];
            float h = tf32r(v);
            ((float*)&qh)[i] = h; ((float*)&ql)[i] = tf32r(v - h);
            v = sk[(4 * cf + i) * 65 + n];
            h = tf32r(v);
            ((float*)&kh)[i] = h; ((float*)&kl)[i] = tf32r(v - h);
        }
        *(float4*)(g_qh + ob + n * CQ + 4 * cf) = qh;
        *(float4*)(g_ql + ob + n * CQ + 4 * cf) = ql;
        *(float4*)(g_kh + ob + n * CQ + 4 * cf) = kh;
        *(float4*)(g_kl + ob + n * CQ + 4 * cf) = kl;
    }
}

// ============ Kernel 1c: V transpose -> [b][n][o], tf32-rounded ============
__global__ __launch_bounds__(256) void vt_kernel()
{
    __shared__ float sT[64 * 65];
    const int n0 = blockIdx.x * 64, o0 = blockIdx.y * 64, b = blockIdx.z;
    const int t = threadIdx.x;
    const float* src = g_v  + (size_t)b * CC * NTOK;
    float*       dst = g_vt + (size_t)b * NTOK * CC;
#pragma unroll
    for (int p = 0; p < 4; p++) {
        int idx = p * 256 + t, o = idx >> 4, k = idx & 15;
        float4 v = *(const float4*)(src + (size_t)(o0 + o) * NTOK + n0 + 4 * k);
        sT[o * 65 + 4 * k + 0] = v.x; sT[o * 65 + 4 * k + 1] = v.y;
        sT[o * 65 + 4 * k + 2] = v.z; sT[o * 65 + 4 * k + 3] = v.w;
    }
    __syncthreads();
#pragma unroll
    for (int p = 0; p < 4; p++) {
        int idx = p * 256 + t, n = idx >> 4, k = idx & 15;
        float4 w = {tf32r(sT[(4 * k + 0) * 65 + n]), tf32r(sT[(4 * k + 1) * 65 + n]),
                    tf32r(sT[(4 * k + 2) * 65 + n]), tf32r(sT[(4 * k + 3) * 65 + n])};
        *(float4*)(dst + (size_t)(n0 + n) * CC + o0 + 4 * k) = w;
    }
}

// ============ Kernel 2: flash attention on tensor cores (tf32 mma) ============
// smem: sQh[64*36] sQl[64*36] sKh[32*36] sKl[32*36] sV[32*264] sP[64*36] sAl[64] sSc[64]
#define OQH 0
#define OQL 2304
#define OKH 4608
#define OKL 5760
#define OV  6912
#define OP  15360
#define OAL 17664
#define OSC 17728
#define SMEM_FLOATS 17792

__global__ __launch_bounds__(256, 2) void attn_kernel(
    const float* __restrict__ x,
    const float* __restrict__ gamma,
    float* __restrict__ out)
{
    extern __shared__ float sm[];
    float* sQh = sm + OQH;  float* sQl = sm + OQL;
    float* sKh = sm + OKH;  float* sKl = sm + OKL;
    float* sV  = sm + OV;   float* sP  = sm + OP;
    float* sAl = sm + OAL;  float* sSc = sm + OSC;
    const unsigned* uQh = (const unsigned*)sQh;
    const unsigned* uQl = (const unsigned*)sQl;
    const unsigned* uKh = (const unsigned*)sKh;
    const unsigned* uKl = (const unsigned*)sKl;
    const unsigned* uV  = (const unsigned*)sV;
    const unsigned* uP  = (const unsigned*)sP;

    const int t = threadIdx.x, w = t >> 5, lane = t & 31;
    const int quad = lane & 3, qr = lane >> 2;
    const int m_base = 32 * (w >> 2), o_base = 64 * (w & 3);
    const int b = blockIdx.x >> 6, q0 = (blockIdx.x & 63) * 64;

    const float* qhp = g_qh + ((size_t)b * NTOK + q0) * CQ;
    const float* qlp = g_ql + ((size_t)b * NTOK + q0) * CQ;
    const float* khp = g_kh + (size_t)b * NTOK * CQ;
    const float* klp = g_kl + (size_t)b * NTOK * CQ;
    const float* vp  = g_vt + (size_t)b * NTOK * CC;

    // load Q tile (64 x 32), hi+lo
#pragma unroll
    for (int p = 0; p < 2; p++) {
        int idx = p * 256 + t, n = idx >> 3, c4 = idx & 7;
        *(float4*)(sQh + n * 36 + 4 * c4) = *(const float4*)(qhp + n * CQ + 4 * c4);
        *(float4*)(sQl + n * 36 + 4 * c4) = *(const float4*)(qlp + n * CQ + 4 * c4);
    }

    float4 acc[2][8];
#pragma unroll
    for (int s = 0; s < 2; s++)
#pragma unroll
        for (int o = 0; o < 8; o++) acc[s][o] = make_float4(0.f, 0.f, 0.f, 0.f);
    float run_mA = -INFINITY, run_mB = -INFINITY, run_lA = 0.f, run_lB = 0.f;

    for (int kt = 0; kt < 128; kt++) {
        int j0 = kt * 32;
        __syncthreads();
        {   // load K tile (32x32 hi/lo) + V tile (32x256)
            int n = t >> 3, c4 = t & 7;
            *(float4*)(sKh + n * 36 + 4 * c4) = *(const float4*)(khp + (size_t)(j0 + n) * CQ + 4 * c4);
            *(float4*)(sKl + n * 36 + 4 * c4) = *(const float4*)(klp + (size_t)(j0 + n) * CQ + 4 * c4);
#pragma unroll
            for (int p = 0; p < 8; p++) {
                int idx = p * 256 + t, vn = idx >> 6, vc = idx & 63;
                *(float4*)(sV + vn * 264 + 4 * vc) = *(const float4*)(vp + (size_t)(j0 + vn) * CC + 4 * vc);
            }
        }
        __syncthreads();

        if (w < 4) {   // S + softmax for rows 16w..16w+15
            unsigned ah[4][4], al[4][4];
#pragma unroll
            for (int ks = 0; ks < 4; ks++) {
                int base = (16 * w + qr) * 36 + ks * 8 + quad;
                ah[ks][0] = uQh[base];          ah[ks][1] = uQh[base + 8 * 36];
                ah[ks][2] = uQh[base + 4];      ah[ks][3] = uQh[base + 8 * 36 + 4];
                al[ks][0] = uQl[base];          al[ks][1] = uQl[base + 8 * 36];
                al[ks][2] = uQl[base + 4];      al[ks][3] = uQl[base + 8 * 36 + 4];
            }
            float4 sreg[4];
#pragma unroll
            for (int nt = 0; nt < 4; nt++) {
                float4 c = make_float4(0.f, 0.f, 0.f, 0.f);
#pragma unroll
                for (int ks = 0; ks < 4; ks++) {
                    int kb = (nt * 8 + qr) * 36 + ks * 8 + quad;
                    unsigned bh0 = uKh[kb], bh1 = uKh[kb + 4];
                    unsigned bl0 = uKl[kb], bl1 = uKl[kb + 4];
                    mma8(c, ah[ks], bh0, bh1);
                    mma8(c, al[ks], bh0, bh1);
                    mma8(c, ah[ks], bl0, bl1);
                }
                sreg[nt] = c;
            }
            float mA = -INFINITY, mB = -INFINITY;
#pragma unroll
            for (int nt = 0; nt < 4; nt++) {
                mA = fmaxf(mA, fmaxf(sreg[nt].x, sreg[nt].y));
                mB = fmaxf(mB, fmaxf(sreg[nt].z, sreg[nt].w));
            }
            mA = fmaxf(mA, __shfl_xor_sync(0xffffffffu, mA, 1));
            mA = fmaxf(mA, __shfl_xor_sync(0xffffffffu, mA, 2));
            mB = fmaxf(mB, __shfl_xor_sync(0xffffffffu, mB, 1));
            mB = fmaxf(mB, __shfl_xor_sync(0xffffffffu, mB, 2));
            float mAn = fmaxf(run_mA, mA), mBn = fmaxf(run_mB, mB);
            float alA = __expf(run_mA - mAn), alB = __expf(run_mB - mBn);
            run_mA = mAn; run_mB = mBn;
            float sA = 0.f, sB = 0.f;
#pragma unroll
            for (int nt = 0; nt < 4; nt++) {
                float px = __expf(sreg[nt].x - mAn), py = __expf(sreg[nt].y - mAn);
                float pz = __expf(sreg[nt].z - mBn), pw = __expf(sreg[nt].w - mBn);
                sA += px + py; sB += pz + pw;
                int pb = (16 * w + qr) * 36 + nt * 8 + 2 * quad;
                *(float2*)(sP + pb) = make_float2(tf32r(px), tf32r(py));
                *(float2*)(sP + pb + 8 * 36) = make_float2(tf32r(pz), tf32r(pw));
            }
            sA += __shfl_xor_sync(0xffffffffu, sA, 1);
            sA += __shfl_xor_sync(0xffffffffu, sA, 2);
            sB += __shfl_xor_sync(0xffffffffu, sB, 1);
            sB += __shfl_xor_sync(0xffffffffu, sB, 2);
            run_lA = run_lA * alA + sA;
            run_lB = run_lB * alB + sB;
            if (quad == 0) { sAl[16 * w + qr] = alA; sAl[16 * w + qr + 8] = alB; }
        }
        __syncthreads();

        // rescale + PV
        float aA0 = sAl[m_base + qr],      aB0 = sAl[m_base + qr + 8];
        float aA1 = sAl[m_base + 16 + qr], aB1 = sAl[m_base + 16 + qr + 8];
#pragma unroll
        for (int o = 0; o < 8; o++) {
            acc[0][o].x *= aA0; acc[0][o].y *= aA0; acc[0][o].z *= aB0; acc[0][o].w *= aB0;
            acc[1][o].x *= aA1; acc[1][o].y *= aA1; acc[1][o].z *= aB1; acc[1][o].w *= aB1;
        }
#pragma unroll
        for (int ks = 0; ks < 4; ks++) {
            unsigned p0[4], p1[4];
            int b0i = (m_base + qr) * 36 + ks * 8 + quad;
            int b1i = (m_base + 16 + qr) * 36 + ks * 8 + quad;
            p0[0] = uP[b0i];     p0[1] = uP[b0i + 8 * 36];
            p0[2] = uP[b0i + 4]; p0[3] = uP[b0i + 8 * 36 + 4];
            p1[0] = uP[b1i];     p1[1] = uP[b1i + 8 * 36];
            p1[2] = uP[b1i + 4]; p1[3] = uP[b1i + 8 * 36 + 4];
#pragma unroll
            for (int ot = 0; ot < 8; ot++) {
                int vb = (ks * 8 + quad) * 264 + o_base + ot * 8 + qr;
                unsigned v0 = uV[vb], v1 = uV[vb + 4 * 264];
                mma8(acc[0][ot], p0, v0, v1);
                mma8(acc[1][ot], p1, v0, v1);
            }
        }
    }

    __syncthreads();
    if (w < 4 && quad == 0) {
        float gm = gamma[0];
        sSc[16 * w + qr]     = gm / run_lA;
        sSc[16 * w + qr + 8] = gm / run_lB;
    }
    __syncthreads();

    const float* xb = x   + (size_t)b * CC * NTOK;
    float*       ob = out + (size_t)b * CC * NTOK;
#pragma unroll
    for (int s = 0; s < 2; s++) {
        float scA = sSc[m_base + 16 * s + qr], scB = sSc[m_base + 16 * s + qr + 8];
        int m = q0 + m_base + 16 * s + qr;
#pragma unroll
        for (int ot = 0; ot < 8; ot++) {
            int o = o_base + ot * 8 + 2 * quad;
            float4 c = acc[s][ot];
            size_t i00 = (size_t)o * NTOK + m;
            size_t i10 = (size_t)(o + 1) * NTOK + m;
            ob[i00]     = fmaf(scA, c.x, xb[i00]);
            ob[i10]     = fmaf(scA, c.y, xb[i10]);
            ob[i00 + 8] = fmaf(scB, c.z, xb[i00 + 8]);
            ob[i10 + 8] = fmaf(scB, c.w, xb[i10 + 8]);
        }
    }
}

// ============ launch ============
extern "C" void kernel_launch(void* const* d_in, const int* in_sizes, int n_in,
                              void* d_out, int out_size)
{
    const float* x     = (const float*)d_in[0];
    const float* wq    = (const float*)d_in[1];
    const float* bq    = (const float*)d_in[2];
    const float* wk    = (const float*)d_in[3];
    const float* bk    = (const float*)d_in[4];
    const float* wv    = (const float*)d_in[5];
    const float* bv    = (const float*)d_in[6];
    const float* gamma = (const float*)d_in[7];
    float* out = (float*)d_out;

    dim3 pgrid(NTOK / 128, 5, BATCH);
    proj_kernel<<<pgrid, 256>>>(x, wq, bq, wk, bk, wv, bv);

    tqk_kernel<<<dim3(NTOK / 64, BATCH), 256>>>();
    vt_kernel<<<dim3(NTOK / 64, CC / 64, BATCH), 256>>>();

    const int smem_bytes = SMEM_FLOATS * (int)sizeof(float);  // 71168
    cudaFuncSetAttribute(attn_kernel, cudaFuncAttributeMaxDynamicSharedMemorySize, smem_bytes);
    attn_kernel<<<BATCH * (NTOK / 64), 256, smem_bytes>>>(x, gamma, out);
}

// round 7
// speedup vs baseline: 2.9306x; 1.1344x over previous
#include <cuda_runtime.h>
#include <cuda_fp16.h>
#include <math.h>

#define BATCH 4
#define CC    256
#define CQ    32
#define NTOK  4096

__device__ float  g_qh[BATCH * NTOK * CQ];
__device__ float  g_ql[BATCH * NTOK * CQ];
__device__ float  g_kh[BATCH * NTOK * CQ];
__device__ float  g_kl[BATCH * NTOK * CQ];
__device__ __half g_vh[BATCH * CC * NTOK];   // [b][o][n] fp16

__device__ __forceinline__ float tf32r(float v) {
    unsigned r; asm("cvt.rna.tf32.f32 %0, %1;" : "=r"(r) : "f"(v));
    return __uint_as_float(r);
}
__device__ __forceinline__ void mma8(float4& d, const unsigned* a, unsigned b0, unsigned b1) {
    asm volatile(
        "mma.sync.aligned.m16n8k8.row.col.f32.tf32.tf32.f32 "
        "{%0,%1,%2,%3},{%4,%5,%6,%7},{%8,%9},{%0,%1,%2,%3};"
        : "+f"(d.x), "+f"(d.y), "+f"(d.z), "+f"(d.w)
        : "r"(a[0]), "r"(a[1]), "r"(a[2]), "r"(a[3]), "r"(b0), "r"(b1));
}
__device__ __forceinline__ void mma16(float4& d, const unsigned* a, unsigned b0, unsigned b1) {
    asm volatile(
        "mma.sync.aligned.m16n8k16.row.col.f32.f16.f16.f32 "
        "{%0,%1,%2,%3},{%4,%5,%6,%7},{%8,%9},{%0,%1,%2,%3};"
        : "+f"(d.x), "+f"(d.y), "+f"(d.z), "+f"(d.w)
        : "r"(a[0]), "r"(a[1]), "r"(a[2]), "r"(a[3]), "r"(b0), "r"(b1));
}

// ============ Kernel 1: projections + layout production ============
__global__ __launch_bounds__(256) void proj_kernel(
    const float* __restrict__ x,
    const float* __restrict__ wq, const float* __restrict__ bq,
    const float* __restrict__ wk, const float* __restrict__ bk,
    const float* __restrict__ wv, const float* __restrict__ bv)
{
    __shared__ float sX[32 * 128];
    __shared__ float sW[32 * 68];
    const int n0 = blockIdx.x * 128, r0 = blockIdx.y * 64, b = blockIdx.z;
    const int t = threadIdx.x, rg = t >> 4, ng = t & 15;
    float acc[4][8];
#pragma unroll
    for (int j = 0; j < 4; j++)
#pragma unroll
        for (int i = 0; i < 8; i++) acc[j][i] = 0.0f;
    for (int cc = 0; cc < CC; cc += 32) {
#pragma unroll
        for (int p = 0; p < 4; p++) {
            int idx = p * 256 + t, cr = idx >> 5, l = idx & 31;
            float4 v = *(const float4*)(x + ((size_t)b * CC + cc + cr) * NTOK + n0 + 4 * l);
            *(float4*)(sX + cr * 128 + 4 * l) = v;
        }
#pragma unroll
        for (int p = 0; p < 2; p++) {
            int idx = p * 256 + t, rl = idx >> 3, cf = idx & 7;
            int rglob = r0 + rl;
            const float* wrow;
            if (rglob < CQ)          wrow = wq + (size_t)rglob * CC;
            else if (rglob < 2 * CQ) wrow = wk + (size_t)(rglob - CQ) * CC;
            else                     wrow = wv + (size_t)(rglob - 2 * CQ) * CC;
            float4 v = *(const float4*)(wrow + cc + 4 * cf);
            sW[(4 * cf + 0) * 68 + rl] = v.x;
            sW[(4 * cf + 1) * 68 + rl] = v.y;
            sW[(4 * cf + 2) * 68 + rl] = v.z;
            sW[(4 * cf + 3) * 68 + rl] = v.w;
        }
        __syncthreads();
#pragma unroll
        for (int c = 0; c < 32; c++) {
            float4 w  = *(float4*)(sW + c * 68 + 4 * rg);
            float4 x1 = *(float4*)(sX + c * 128 + 4 * ng);
            float4 x2 = *(float4*)(sX + c * 128 + 64 + 4 * ng);
            float wj[4] = {w.x, w.y, w.z, w.w};
            float xs[8] = {x1.x, x1.y, x1.z, x1.w, x2.x, x2.y, x2.z, x2.w};
#pragma unroll
            for (int j = 0; j < 4; j++)
#pragma unroll
                for (int i = 0; i < 8; i++) acc[j][i] = fmaf(wj[j], xs[i], acc[j][i]);
        }
        __syncthreads();
    }
#pragma unroll
    for (int j = 0; j < 4; j++) {
        int rglob = r0 + 4 * rg + j;
        if (rglob < 2 * CQ) {
            bool isq = rglob < CQ;
            int c = isq ? rglob : rglob - CQ;
            float bias = isq ? bq[c] : bk[c];
            float* dh = (isq ? g_qh : g_kh) + (size_t)b * NTOK * CQ + c;
            float* dl = (isq ? g_ql : g_kl) + (size_t)b * NTOK * CQ + c;
#pragma unroll
            for (int i = 0; i < 8; i++) {
                int n = (i < 4) ? (n0 + 4 * ng + i) : (n0 + 64 + 4 * ng + i - 4);
                float v = acc[j][i] + bias;
                float h = tf32r(v);
                dh[(size_t)n * CQ] = h;
                dl[(size_t)n * CQ] = tf32r(v - h);
            }
        } else {
            int o = rglob - 2 * CQ;
            float bias = bv[o];
            __half* dst = g_vh + ((size_t)b * CC + o) * NTOK;
            __half2 h0 = __floats2half2_rn(acc[j][0] + bias, acc[j][1] + bias);
            __half2 h1 = __floats2half2_rn(acc[j][2] + bias, acc[j][3] + bias);
            __half2 h2 = __floats2half2_rn(acc[j][4] + bias, acc[j][5] + bias);
            __half2 h3 = __floats2half2_rn(acc[j][6] + bias, acc[j][7] + bias);
            *(__half2*)(dst + n0 + 4 * ng)          = h0;
            *(__half2*)(dst + n0 + 4 * ng + 2)      = h1;
            *(__half2*)(dst + n0 + 64 + 4 * ng)     = h2;
            *(__half2*)(dst + n0 + 64 + 4 * ng + 2) = h3;
        }
    }
}

// ============ Kernel 2: flash attention (3xTF32 S, fp16 PV) ============
// word offsets: Qh[64*36] Ql[64*36] Kh[32*36] Kl[32*36] V[256*20] P[64*20] Al[64] Sc[64]
#define OQH 0
#define OQL 2304
#define OKH 4608
#define OKL 5760
#define OV  6912
#define OP  12032
#define OAL 13312
#define OSC 13376
#define SMEM_FLOATS 13440

__global__ __launch_bounds__(256, 2) void attn_kernel(
    const float* __restrict__ x,
    const float* __restrict__ gamma,
    float* __restrict__ out)
{
    extern __shared__ float sm[];
    float* sQh = sm + OQH;  float* sQl = sm + OQL;
    float* sKh = sm + OKH;  float* sKl = sm + OKL;
    unsigned* uV = (unsigned*)(sm + OV);
    unsigned* uP = (unsigned*)(sm + OP);
    float* sAl = sm + OAL;  float* sSc = sm + OSC;
    const unsigned* uQh = (const unsigned*)sQh;
    const unsigned* uQl = (const unsigned*)sQl;
    const unsigned* uKh = (const unsigned*)sKh;
    const unsigned* uKl = (const unsigned*)sKl;

    const int t = threadIdx.x, w = t >> 5, lane = t & 31;
    const int quad = lane & 3, qr = lane >> 2;
    const int m_base = 32 * (w >> 2), o_base = 64 * (w & 3);
    const int b = blockIdx.x >> 6, q0 = (blockIdx.x & 63) * 64;

    const float* qhp = g_qh + ((size_t)b * NTOK + q0) * CQ;
    const float* qlp = g_ql + ((size_t)b * NTOK + q0) * CQ;
    const float* khp = g_kh + (size_t)b * NTOK * CQ;
    const float* klp = g_kl + (size_t)b * NTOK * CQ;
    const __half* vph = g_vh + (size_t)b * CC * NTOK;

    // load Q tile (64 x 32), hi+lo
#pragma unroll
    for (int p = 0; p < 2; p++) {
        int idx = p * 256 + t, n = idx >> 3, c4 = idx & 7;
        *(float4*)(sQh + n * 36 + 4 * c4) = *(const float4*)(qhp + n * CQ + 4 * c4);
        *(float4*)(sQl + n * 36 + 4 * c4) = *(const float4*)(qlp + n * CQ + 4 * c4);
    }

    float4 acc[2][8];
#pragma unroll
    for (int s = 0; s < 2; s++)
#pragma unroll
        for (int o = 0; o < 8; o++) acc[s][o] = make_float4(0.f, 0.f, 0.f, 0.f);
    float run_mA = -INFINITY, run_mB = -INFINITY, run_lA = 0.f, run_lB = 0.f;

    for (int kt = 0; kt < 128; kt++) {
        int j0 = kt * 32;
        __syncthreads();
        {   // K tile (32x32 hi/lo, tf32) ; V tile (256 o x 32 k, fp16 [o][k])
            int n = t >> 3, c4 = t & 7;
            *(float4*)(sKh + n * 36 + 4 * c4) = *(const float4*)(khp + (size_t)(j0 + n) * CQ + 4 * c4);
            *(float4*)(sKl + n * 36 + 4 * c4) = *(const float4*)(klp + (size_t)(j0 + n) * CQ + 4 * c4);
#pragma unroll
            for (int p = 0; p < 2; p++) {
                int j = p * 256 + t, o = j >> 1, h = j & 1;
                const uint4* src = (const uint4*)(vph + (size_t)o * NTOK + j0 + h * 16);
                uint4 wa = src[0], wb = src[1];
                *(uint4*)(uV + o * 20 + h * 8)     = wa;
                *(uint4*)(uV + o * 20 + h * 8 + 4) = wb;
            }
        }
        __syncthreads();

        if (w < 4) {   // S + softmax for rows 16w..16w+15
            unsigned ah[4][4], al[4][4];
#pragma unroll
            for (int ks = 0; ks < 4; ks++) {
                int base = (16 * w + qr) * 36 + ks * 8 + quad;
                ah[ks][0] = uQh[base];          ah[ks][1] = uQh[base + 8 * 36];
                ah[ks][2] = uQh[base + 4];      ah[ks][3] = uQh[base + 8 * 36 + 4];
                al[ks][0] = uQl[base];          al[ks][1] = uQl[base + 8 * 36];
                al[ks][2] = uQl[base + 4];      al[ks][3] = uQl[base + 8 * 36 + 4];
            }
            float4 sreg[4];
#pragma unroll
            for (int nt = 0; nt < 4; nt++) {
                float4 c = make_float4(0.f, 0.f, 0.f, 0.f);
#pragma unroll
                for (int ks = 0; ks < 4; ks++) {
                    int kb = (nt * 8 + qr) * 36 + ks * 8 + quad;
                    unsigned bh0 = uKh[kb], bh1 = uKh[kb + 4];
                    unsigned bl0 = uKl[kb], bl1 = uKl[kb + 4];
                    mma8(c, ah[ks], bh0, bh1);
                    mma8(c, al[ks], bh0, bh1);
                    mma8(c, ah[ks], bl0, bl1);
                }
                sreg[nt] = c;
            }
            float mA = -INFINITY, mB = -INFINITY;
#pragma unroll
            for (int nt = 0; nt < 4; nt++) {
                mA = fmaxf(mA, fmaxf(sreg[nt].x, sreg[nt].y));
                mB = fmaxf(mB, fmaxf(sreg[nt].z, sreg[nt].w));
            }
            mA = fmaxf(mA, __shfl_xor_sync(0xffffffffu, mA, 1));
            mA = fmaxf(mA, __shfl_xor_sync(0xffffffffu, mA, 2));
            mB = fmaxf(mB, __shfl_xor_sync(0xffffffffu, mB, 1));
            mB = fmaxf(mB, __shfl_xor_sync(0xffffffffu, mB, 2));
            float mAn = fmaxf(run_mA, mA), mBn = fmaxf(run_mB, mB);
            float alA = __expf(run_mA - mAn), alB = __expf(run_mB - mBn);
            run_mA = mAn; run_mB = mBn;
            float sA = 0.f, sB = 0.f;
#pragma unroll
            for (int nt = 0; nt < 4; nt++) {
                float px = __expf(sreg[nt].x - mAn), py = __expf(sreg[nt].y - mAn);
                float pz = __expf(sreg[nt].z - mBn), pw = __expf(sreg[nt].w - mBn);
                sA += px + py; sB += pz + pw;
                __half2 hA = __floats2half2_rn(px, py);
                __half2 hB = __floats2half2_rn(pz, pw);
                uP[(16 * w + qr) * 20 + nt * 4 + quad]     = *(unsigned*)&hA;
                uP[(16 * w + qr + 8) * 20 + nt * 4 + quad] = *(unsigned*)&hB;
            }
            sA += __shfl_xor_sync(0xffffffffu, sA, 1);
            sA += __shfl_xor_sync(0xffffffffu, sA, 2);
            sB += __shfl_xor_sync(0xffffffffu, sB, 1);
            sB += __shfl_xor_sync(0xffffffffu, sB, 2);
            run_lA = run_lA * alA + sA;
            run_lB = run_lB * alB + sB;
            if (quad == 0) { sAl[16 * w + qr] = alA; sAl[16 * w + qr + 8] = alB; }
        }
        __syncthreads();

        // rescale + PV (fp16, m16n8k16)
        float aA0 = sAl[m_base + qr],      aB0 = sAl[m_base + qr + 8];
        float aA1 = sAl[m_base + 16 + qr], aB1 = sAl[m_base + 16 + qr + 8];
#pragma unroll
        for (int o = 0; o < 8; o++) {
            acc[0][o].x *= aA0; acc[0][o].y *= aA0; acc[0][o].z *= aB0; acc[0][o].w *= aB0;
            acc[1][o].x *= aA1; acc[1][o].y *= aA1; acc[1][o].z *= aB1; acc[1][o].w *= aB1;
        }
#pragma unroll
        for (int ks = 0; ks < 2; ks++) {
            unsigned p0[4], p1[4];
            int a0i = (m_base + qr) * 20 + ks * 8 + quad;
            p0[0] = uP[a0i];           p0[1] = uP[a0i + 8 * 20];
            p0[2] = uP[a0i + 4];       p0[3] = uP[a0i + 8 * 20 + 4];
            int a1i = (m_base + 16 + qr) * 20 + ks * 8 + quad;
            p1[0] = uP[a1i];           p1[1] = uP[a1i + 8 * 20];
            p1[2] = uP[a1i + 4];       p1[3] = uP[a1i + 8 * 20 + 4];
#pragma unroll
            for (int ot = 0; ot < 8; ot++) {
                int vi = (o_base + ot * 8 + qr) * 20 + ks * 8 + quad;
                unsigned v0 = uV[vi], v1 = uV[vi + 4];
                mma16(acc[0][ot], p0, v0, v1);
                mma16(acc[1][ot], p1, v0, v1);
            }
        }
    }

    __syncthreads();
    if (w < 4 && quad == 0) {
        float gm = gamma[0];
        sSc[16 * w + qr]     = gm / run_lA;
        sSc[16 * w + qr + 8] = gm / run_lB;
    }
    __syncthreads();

    const float* xb = x   + (size_t)b * CC * NTOK;
    float*       ob = out + (size_t)b * CC * NTOK;
#pragma unroll
    for (int s = 0; s < 2; s++) {
        float scA = sSc[m_base + 16 * s + qr], scB = sSc[m_base + 16 * s + qr + 8];
        int m = q0 + m_base + 16 * s + qr;
#pragma unroll
        for (int ot = 0; ot < 8; ot++) {
            int o = o_base + ot * 8 + 2 * quad;
            float4 c = acc[s][ot];
            size_t i00 = (size_t)o * NTOK + m;
            size_t i10 = (size_t)(o + 1) * NTOK + m;
            ob[i00]     = fmaf(scA, c.x, xb[i00]);
            ob[i10]     = fmaf(scA, c.y, xb[i10]);
            ob[i00 + 8] = fmaf(scB, c.z, xb[i00 + 8]);
            ob[i10 + 8] = fmaf(scB, c.w, xb[i10 + 8]);
        }
    }
}

// ============ launch ============
extern "C" void kernel_launch(void* const* d_in, const int* in_sizes, int n_in,
                              void* d_out, int out_size)
{
    const float* x     = (const float*)d_in[0];
    const float* wq    = (const float*)d_in[1];
    const float* bq    = (const float*)d_in[2];
    const float* wk    = (const float*)d_in[3];
    const float* bk    = (const float*)d_in[4];
    const float* wv    = (const float*)d_in[5];
    const float* bv    = (const float*)d_in[6];
    const float* gamma = (const float*)d_in[7];
    float* out = (float*)d_out;

    dim3 pgrid(NTOK / 128, 5, BATCH);
    proj_kernel<<<pgrid, 256>>>(x, wq, bq, wk, bk, wv, bv);

    const int smem_bytes = SMEM_FLOATS * (int)sizeof(float);  // 53760
    cudaFuncSetAttribute(attn_kernel, cudaFuncAttributeMaxDynamicSharedMemorySize, smem_bytes);
    attn_kernel<<<BATCH * (NTOK / 64), 256, smem_bytes>>>(x, gamma, out);
}

// round 8
// speedup vs baseline: 3.2533x; 1.1101x over previous
#include <cuda_runtime.h>
#include <cuda_fp16.h>
#include <math.h>

#define BATCH 4
#define CC    256
#define CQ    32
#define NTOK  4096

__device__ __half g_qh[BATCH * NTOK * CQ];
__device__ __half g_ql[BATCH * NTOK * CQ];
__device__ __half g_kh[BATCH * NTOK * CQ];
__device__ __half g_kl[BATCH * NTOK * CQ];
__device__ __half g_vh[BATCH * CC * NTOK];   // [b][o][n] fp16

__device__ __forceinline__ void mma16(float4& d, const unsigned* a, unsigned b0, unsigned b1) {
    asm volatile(
        "mma.sync.aligned.m16n8k16.row.col.f32.f16.f16.f32 "
        "{%0,%1,%2,%3},{%4,%5,%6,%7},{%8,%9},{%0,%1,%2,%3};"
        : "+f"(d.x), "+f"(d.y), "+f"(d.z), "+f"(d.w)
        : "r"(a[0]), "r"(a[1]), "r"(a[2]), "r"(a[3]), "r"(b0), "r"(b1));
}

// ============ Kernel 1: projections + fp16 layout production ============
__global__ __launch_bounds__(256) void proj_kernel(
    const float* __restrict__ x,
    const float* __restrict__ wq, const float* __restrict__ bq,
    const float* __restrict__ wk, const float* __restrict__ bk,
    const float* __restrict__ wv, const float* __restrict__ bv)
{
    __shared__ float sX[32 * 128];
    __shared__ float sW[32 * 68];
    const int n0 = blockIdx.x * 128, r0 = blockIdx.y * 64, b = blockIdx.z;
    const int t = threadIdx.x, rg = t >> 4, ng = t & 15;
    float acc[4][8];
#pragma unroll
    for (int j = 0; j < 4; j++)
#pragma unroll
        for (int i = 0; i < 8; i++) acc[j][i] = 0.0f;
    for (int cc = 0; cc < CC; cc += 32) {
#pragma unroll
        for (int p = 0; p < 4; p++) {
            int idx = p * 256 + t, cr = idx >> 5, l = idx & 31;
            float4 v = *(const float4*)(x + ((size_t)b * CC + cc + cr) * NTOK + n0 + 4 * l);
            *(float4*)(sX + cr * 128 + 4 * l) = v;
        }
#pragma unroll
        for (int p = 0; p < 2; p++) {
            int idx = p * 256 + t, rl = idx >> 3, cf = idx & 7;
            int rglob = r0 + rl;
            const float* wrow;
            if (rglob < CQ)          wrow = wq + (size_t)rglob * CC;
            else if (rglob < 2 * CQ) wrow = wk + (size_t)(rglob - CQ) * CC;
            else                     wrow = wv + (size_t)(rglob - 2 * CQ) * CC;
            float4 v = *(const float4*)(wrow + cc + 4 * cf);
            sW[(4 * cf + 0) * 68 + rl] = v.x;
            sW[(4 * cf + 1) * 68 + rl] = v.y;
            sW[(4 * cf + 2) * 68 + rl] = v.z;
            sW[(4 * cf + 3) * 68 + rl] = v.w;
        }
        __syncthreads();
#pragma unroll
        for (int c = 0; c < 32; c++) {
            float4 w  = *(float4*)(sW + c * 68 + 4 * rg);
            float4 x1 = *(float4*)(sX + c * 128 + 4 * ng);
            float4 x2 = *(float4*)(sX + c * 128 + 64 + 4 * ng);
            float wj[4] = {w.x, w.y, w.z, w.w};
            float xs[8] = {x1.x, x1.y, x1.z, x1.w, x2.x, x2.y, x2.z, x2.w};
#pragma unroll
            for (int j = 0; j < 4; j++)
#pragma unroll
                for (int i = 0; i < 8; i++) acc[j][i] = fmaf(wj[j], xs[i], acc[j][i]);
        }
        __syncthreads();
    }
#pragma unroll
    for (int j = 0; j < 4; j++) {
        int rglob = r0 + 4 * rg + j;
        if (rglob < 2 * CQ) {
            bool isq = rglob < CQ;
            int c = isq ? rglob : rglob - CQ;
            float bias = isq ? bq[c] : bk[c];
            __half* dh = (isq ? g_qh : g_kh) + (size_t)b * NTOK * CQ + c;
            __half* dl = (isq ? g_ql : g_kl) + (size_t)b * NTOK * CQ + c;
#pragma unroll
            for (int i = 0; i < 8; i++) {
                int n = (i < 4) ? (n0 + 4 * ng + i) : (n0 + 64 + 4 * ng + i - 4);
                float v = acc[j][i] + bias;
                __half h = __float2half_rn(v);
                dh[(size_t)n * CQ] = h;
                dl[(size_t)n * CQ] = __float2half_rn(v - __half2float(h));
            }
        } else {
            int o = rglob - 2 * CQ;
            float bias = bv[o];
            __half* dst = g_vh + ((size_t)b * CC + o) * NTOK;
            __half2 h0 = __floats2half2_rn(acc[j][0] + bias, acc[j][1] + bias);
            __half2 h1 = __floats2half2_rn(acc[j][2] + bias, acc[j][3] + bias);
            __half2 h2 = __floats2half2_rn(acc[j][4] + bias, acc[j][5] + bias);
            __half2 h3 = __floats2half2_rn(acc[j][6] + bias, acc[j][7] + bias);
            *(__half2*)(dst + n0 + 4 * ng)          = h0;
            *(__half2*)(dst + n0 + 4 * ng + 2)      = h1;
            *(__half2*)(dst + n0 + 64 + 4 * ng)     = h2;
            *(__half2*)(dst + n0 + 64 + 4 * ng + 2) = h3;
        }
    }
}

// ============ Kernel 2: flash attention (fp16 3-split S, fp16 PV) ============
// word offsets: Qh[64*20] Ql[64*20] Kh[32*20] Kl[32*20] V[256*20] P[64*20] Al Sc
#define OQH 0
#define OQL 1280
#define OKH 2560
#define OKL 3200
#define OV  3840
#define OP  8960
#define OAL 10240
#define OSC 10304
#define SMEM_WORDS 10368

__global__ __launch_bounds__(256, 2) void attn_kernel(
    const float* __restrict__ x,
    const float* __restrict__ gamma,
    float* __restrict__ out)
{
    extern __shared__ unsigned su[];
    unsigned* uQh = su + OQH;  unsigned* uQl = su + OQL;
    unsigned* uKh = su + OKH;  unsigned* uKl = su + OKL;
    unsigned* uV  = su + OV;   unsigned* uP  = su + OP;
    float* sAl = (float*)(su + OAL);
    float* sSc = (float*)(su + OSC);

    const int t = threadIdx.x, w = t >> 5, lane = t & 31;
    const int quad = lane & 3, qr = lane >> 2;
    const int m_base = 32 * (w >> 2), o_base = 64 * (w & 3);
    const int b = blockIdx.x >> 6, q0 = (blockIdx.x & 63) * 64;

    // ---- Q staging (once): fp16 hi/lo, stride-20-word rows ----
    {
        int r = t >> 2, qw = t & 3;
        size_t off = ((size_t)b * NTOK + q0 + r) * CQ + qw * 8;
        *(uint4*)(uQh + r * 20 + qw * 4) = *(const uint4*)(g_qh + off);
        *(uint4*)(uQl + r * 20 + qw * 4) = *(const uint4*)(g_ql + off);
    }

    // ---- prefetch pointers ----
    const int kpl = t >> 7, kr = (t >> 2) & 31, kqw = t & 3;
    const __half* kbase = (kpl ? g_kl : g_kh) + (size_t)b * NTOK * CQ + (size_t)kr * CQ + kqw * 8;
    unsigned* kdst = (kpl ? uKl : uKh) + kr * 20 + kqw * 4;

    const __half* vb = g_vh + (size_t)b * CC * NTOK;
    const int vo0 = t >> 1, vh = t & 1, vo1 = 128 + (t >> 1);
    const __half* vsrc0 = vb + (size_t)vo0 * NTOK + vh * 16;
    const __half* vsrc1 = vb + (size_t)vo1 * NTOK + vh * 16;
    unsigned* vdst0 = uV + vo0 * 20 + vh * 8;
    unsigned* vdst1 = uV + vo1 * 20 + vh * 8;

    uint4 kreg, v0a, v0b, v1a, v1b;
    // prefetch tile 0
    kreg = *(const uint4*)(kbase);
    v0a = ((const uint4*)vsrc0)[0]; v0b = ((const uint4*)vsrc0)[1];
    v1a = ((const uint4*)vsrc1)[0]; v1b = ((const uint4*)vsrc1)[1];

    float4 acc[2][8];
#pragma unroll
    for (int s = 0; s < 2; s++)
#pragma unroll
        for (int o = 0; o < 8; o++) acc[s][o] = make_float4(0.f, 0.f, 0.f, 0.f);
    float run_mA = -INFINITY, run_mB = -INFINITY, run_lA = 0.f, run_lB = 0.f;

    for (int kt = 0; kt < 128; kt++) {
        __syncthreads();   // previous tile fully consumed
        // store staged regs
        *(uint4*)kdst = kreg;
        *(uint4*)vdst0 = v0a; *(uint4*)(vdst0 + 4) = v0b;
        *(uint4*)vdst1 = v1a; *(uint4*)(vdst1 + 4) = v1b;
        // prefetch next tile (wraps at end; last fetch unused)
        {
            int jn = ((kt + 1) & 127) * 32;
            kreg = *(const uint4*)(kbase + (size_t)jn * CQ);
            v0a = ((const uint4*)(vsrc0 + jn))[0]; v0b = ((const uint4*)(vsrc0 + jn))[1];
            v1a = ((const uint4*)(vsrc1 + jn))[0]; v1b = ((const uint4*)(vsrc1 + jn))[1];
        }
        __syncthreads();   // staged data visible

        if (w < 4) {   // S + softmax for rows 16w..16w+15
            unsigned ah[2][4], al[2][4];
#pragma unroll
            for (int ks = 0; ks < 2; ks++) {
                int base = (16 * w + qr) * 20 + ks * 8 + quad;
                ah[ks][0] = uQh[base];       ah[ks][1] = uQh[base + 160];
                ah[ks][2] = uQh[base + 4];   ah[ks][3] = uQh[base + 164];
                al[ks][0] = uQl[base];       al[ks][1] = uQl[base + 160];
                al[ks][2] = uQl[base + 4];   al[ks][3] = uQl[base + 164];
            }
            float4 sreg[4];
#pragma unroll
            for (int nt = 0; nt < 4; nt++) {
                float4 c = make_float4(0.f, 0.f, 0.f, 0.f);
#pragma unroll
                for (int ks = 0; ks < 2; ks++) {
                    int kb = (nt * 8 + qr) * 20 + ks * 8 + quad;
                    unsigned bh0 = uKh[kb], bh1 = uKh[kb + 4];
                    unsigned bl0 = uKl[kb], bl1 = uKl[kb + 4];
                    mma16(c, ah[ks], bh0, bh1);
                    mma16(c, al[ks], bh0, bh1);
                    mma16(c, ah[ks], bl0, bl1);
                }
                sreg[nt] = c;
            }
            float mA = -INFINITY, mB = -INFINITY;
#pragma unroll
            for (int nt = 0; nt < 4; nt++) {
                mA = fmaxf(mA, fmaxf(sreg[nt].x, sreg[nt].y));
                mB = fmaxf(mB, fmaxf(sreg[nt].z, sreg[nt].w));
            }
            mA = fmaxf(mA, __shfl_xor_sync(0xffffffffu, mA, 1));
            mA = fmaxf(mA, __shfl_xor_sync(0xffffffffu, mA, 2));
            mB = fmaxf(mB, __shfl_xor_sync(0xffffffffu, mB, 1));
            mB = fmaxf(mB, __shfl_xor_sync(0xffffffffu, mB, 2));
            float mAn = fmaxf(run_mA, mA), mBn = fmaxf(run_mB, mB);
            float alA = __expf(run_mA - mAn), alB = __expf(run_mB - mBn);
            run_mA = mAn; run_mB = mBn;
            float sA = 0.f, sB = 0.f;
#pragma unroll
            for (int nt = 0; nt < 4; nt++) {
                float px = __expf(sreg[nt].x - mAn), py = __expf(sreg[nt].y - mAn);
                float pz = __expf(sreg[nt].z - mBn), pw = __expf(sreg[nt].w - mBn);
                sA += px + py; sB += pz + pw;
                __half2 hA = __floats2half2_rn(px, py);
                __half2 hB = __floats2half2_rn(pz, pw);
                uP[(16 * w + qr) * 20 + nt * 4 + quad]     = *(unsigned*)&hA;
                uP[(16 * w + qr + 8) * 20 + nt * 4 + quad] = *(unsigned*)&hB;
            }
            sA += __shfl_xor_sync(0xffffffffu, sA, 1);
            sA += __shfl_xor_sync(0xffffffffu, sA, 2);
            sB += __shfl_xor_sync(0xffffffffu, sB, 1);
            sB += __shfl_xor_sync(0xffffffffu, sB, 2);
            run_lA = run_lA * alA + sA;
            run_lB = run_lB * alB + sB;
            if (quad == 0) { sAl[16 * w + qr] = alA; sAl[16 * w + qr + 8] = alB; }
        }
        __syncthreads();

        // rescale + PV (fp16, m16n8k16)
        float aA0 = sAl[m_base + qr],      aB0 = sAl[m_base + qr + 8];
        float aA1 = sAl[m_base + 16 + qr], aB1 = sAl[m_base + 16 + qr + 8];
#pragma unroll
        for (int o = 0; o < 8; o++) {
            acc[0][o].x *= aA0; acc[0][o].y *= aA0; acc[0][o].z *= aB0; acc[0][o].w *= aB0;
            acc[1][o].x *= aA1; acc[1][o].y *= aA1; acc[1][o].z *= aB1; acc[1][o].w *= aB1;
        }
#pragma unroll
        for (int ks = 0; ks < 2; ks++) {
            unsigned p0[4], p1[4];
            int a0i = (m_base + qr) * 20 + ks * 8 + quad;
            p0[0] = uP[a0i];     p0[1] = uP[a0i + 160];
            p0[2] = uP[a0i + 4]; p0[3] = uP[a0i + 164];
            int a1i = (m_base + 16 + qr) * 20 + ks * 8 + quad;
            p1[0] = uP[a1i];     p1[1] = uP[a1i + 160];
            p1[2] = uP[a1i + 4]; p1[3] = uP[a1i + 164];
#pragma unroll
            for (int ot = 0; ot < 8; ot++) {
                int vi = (o_base + ot * 8 + qr) * 20 + ks * 8 + quad;
                unsigned v0 = uV[vi], v1 = uV[vi + 4];
                mma16(acc[0][ot], p0, v0, v1);
                mma16(acc[1][ot], p1, v0, v1);
            }
        }
    }

    __syncthreads();
    if (w < 4 && quad == 0) {
        float gm = gamma[0];
        sSc[16 * w + qr]     = gm / run_lA;
        sSc[16 * w + qr + 8] = gm / run_lB;
    }
    __syncthreads();

    const float* xb = x   + (size_t)b * CC * NTOK;
    float*       ob = out + (size_t)b * CC * NTOK;
#pragma unroll
    for (int s = 0; s < 2; s++) {
        float scA = sSc[m_base + 16 * s + qr], scB = sSc[m_base + 16 * s + qr + 8];
        int m = q0 + m_base + 16 * s + qr;
#pragma unroll
        for (int ot = 0; ot < 8; ot++) {
            int o = o_base + ot * 8 + 2 * quad;
            float4 c = acc[s][ot];
            size_t i00 = (size_t)o * NTOK + m;
            size_t i10 = (size_t)(o + 1) * NTOK + m;
            ob[i00]     = fmaf(scA, c.x, xb[i00]);
            ob[i10]     = fmaf(scA, c.y, xb[i10]);
            ob[i00 + 8] = fmaf(scB, c.z, xb[i00 + 8]);
            ob[i10 + 8] = fmaf(scB, c.w, xb[i10 + 8]);
        }
    }
}

// ============ launch ============
extern "C" void kernel_launch(void* const* d_in, const int* in_sizes, int n_in,
                              void* d_out, int out_size)
{
    const float* x     = (const float*)d_in[0];
    const float* wq    = (const float*)d_in[1];
    const float* bq    = (const float*)d_in[2];
    const float* wk    = (const float*)d_in[3];
    const float* bk    = (const float*)d_in[4];
    const float* wv    = (const float*)d_in[5];
    const float* bv    = (const float*)d_in[6];
    const float* gamma = (const float*)d_in[7];
    float* out = (float*)d_out;

    dim3 pgrid(NTOK / 128, 5, BATCH);
    proj_kernel<<<pgrid, 256>>>(x, wq, bq, wk, bk, wv, bv);

    const int smem_bytes = SMEM_WORDS * 4;   // 41472
    cudaFuncSetAttribute(attn_kernel, cudaFuncAttributeMaxDynamicSharedMemorySize, smem_bytes);
    attn_kernel<<<BATCH * (NTOK / 64), 256, smem_bytes>>>(x, gamma, out);
}

// round 9
// speedup vs baseline: 3.8917x; 1.1962x over previous
#include <cuda_runtime.h>
#include <cuda_fp16.h>
#include <math.h>

#define BATCH 4
#define CC    256
#define CQ    32
#define NTOK  4096

__device__ __half g_qh[BATCH * NTOK * CQ];
__device__ __half g_ql[BATCH * NTOK * CQ];
__device__ __half g_kh[BATCH * NTOK * CQ];
__device__ __half g_kl[BATCH * NTOK * CQ];
__device__ __half g_vh[BATCH * CC * NTOK];   // [b][o][n] fp16

__device__ __forceinline__ void mma16(float4& d, const unsigned* a, unsigned b0, unsigned b1) {
    asm volatile(
        "mma.sync.aligned.m16n8k16.row.col.f32.f16.f16.f32 "
        "{%0,%1,%2,%3},{%4,%5,%6,%7},{%8,%9},{%0,%1,%2,%3};"
        : "+f"(d.x), "+f"(d.y), "+f"(d.z), "+f"(d.w)
        : "r"(a[0]), "r"(a[1]), "r"(a[2]), "r"(a[3]), "r"(b0), "r"(b1));
}
__device__ __forceinline__ void cpa16(unsigned dst, const void* src) {
    asm volatile("cp.async.ca.shared.global [%0], [%1], 16;" :: "r"(dst), "l"(src));
}

// ============ Kernel 1: projections + fp16 layout production ============
__global__ __launch_bounds__(256) void proj_kernel(
    const float* __restrict__ x,
    const float* __restrict__ wq, const float* __restrict__ bq,
    const float* __restrict__ wk, const float* __restrict__ bk,
    const float* __restrict__ wv, const float* __restrict__ bv)
{
    __shared__ float sX[32 * 128];
    __shared__ float sW[32 * 68];
    const int n0 = blockIdx.x * 128, r0 = blockIdx.y * 64, b = blockIdx.z;
    const int t = threadIdx.x, rg = t >> 4, ng = t & 15;
    float acc[4][8];
#pragma unroll
    for (int j = 0; j < 4; j++)
#pragma unroll
        for (int i = 0; i < 8; i++) acc[j][i] = 0.0f;
    for (int cc = 0; cc < CC; cc += 32) {
#pragma unroll
        for (int p = 0; p < 4; p++) {
            int idx = p * 256 + t, cr = idx >> 5, l = idx & 31;
            float4 v = *(const float4*)(x + ((size_t)b * CC + cc + cr) * NTOK + n0 + 4 * l);
            *(float4*)(sX + cr * 128 + 4 * l) = v;
        }
#pragma unroll
        for (int p = 0; p < 2; p++) {
            int idx = p * 256 + t, rl = idx >> 3, cf = idx & 7;
            int rglob = r0 + rl;
            const float* wrow;
            if (rglob < CQ)          wrow = wq + (size_t)rglob * CC;
            else if (rglob < 2 * CQ) wrow = wk + (size_t)(rglob - CQ) * CC;
            else                     wrow = wv + (size_t)(rglob - 2 * CQ) * CC;
            float4 v = *(const float4*)(wrow + cc + 4 * cf);
            sW[(4 * cf + 0) * 68 + rl] = v.x;
            sW[(4 * cf + 1) * 68 + rl] = v.y;
            sW[(4 * cf + 2) * 68 + rl] = v.z;
            sW[(4 * cf + 3) * 68 + rl] = v.w;
        }
        __syncthreads();
#pragma unroll
        for (int c = 0; c < 32; c++) {
            float4 w  = *(float4*)(sW + c * 68 + 4 * rg);
            float4 x1 = *(float4*)(sX + c * 128 + 4 * ng);
            float4 x2 = *(float4*)(sX + c * 128 + 64 + 4 * ng);
            float wj[4] = {w.x, w.y, w.z, w.w};
            float xs[8] = {x1.x, x1.y, x1.z, x1.w, x2.x, x2.y, x2.z, x2.w};
#pragma unroll
            for (int j = 0; j < 4; j++)
#pragma unroll
                for (int i = 0; i < 8; i++) acc[j][i] = fmaf(wj[j], xs[i], acc[j][i]);
        }
        __syncthreads();
    }
#pragma unroll
    for (int j = 0; j < 4; j++) {
        int rglob = r0 + 4 * rg + j;
        if (rglob < 2 * CQ) {
            bool isq = rglob < CQ;
            int c = isq ? rglob : rglob - CQ;
            float bias = isq ? bq[c] : bk[c];
            __half* dh = (isq ? g_qh : g_kh) + (size_t)b * NTOK * CQ + c;
            __half* dl = (isq ? g_ql : g_kl) + (size_t)b * NTOK * CQ + c;
#pragma unroll
            for (int i = 0; i < 8; i++) {
                int n = (i < 4) ? (n0 + 4 * ng + i) : (n0 + 64 + 4 * ng + i - 4);
                float v = acc[j][i] + bias;
                __half h = __float2half_rn(v);
                dh[(size_t)n * CQ] = h;
                dl[(size_t)n * CQ] = __float2half_rn(v - __half2float(h));
            }
        } else {
            int o = rglob - 2 * CQ;
            float bias = bv[o];
            __half* dst = g_vh + ((size_t)b * CC + o) * NTOK;
            __half2 h0 = __floats2half2_rn(acc[j][0] + bias, acc[j][1] + bias);
            __half2 h1 = __floats2half2_rn(acc[j][2] + bias, acc[j][3] + bias);
            __half2 h2 = __floats2half2_rn(acc[j][4] + bias, acc[j][5] + bias);
            __half2 h3 = __floats2half2_rn(acc[j][6] + bias, acc[j][7] + bias);
            *(__half2*)(dst + n0 + 4 * ng)          = h0;
            *(__half2*)(dst + n0 + 4 * ng + 2)      = h1;
            *(__half2*)(dst + n0 + 64 + 4 * ng)     = h2;
            *(__half2*)(dst + n0 + 64 + 4 * ng + 2) = h3;
        }
    }
}

// ============ Kernel 2: flash attention (cp.async double-buffered) ============
// word offsets
#define OQH  0
#define OQL  1280
#define OKH0 2560
#define OKL0 3200
#define OKH1 3840
#define OKL1 4480
#define OV0  5120
#define OV1  10240
#define OP   15360
#define OAL  16640
#define OSC  16704
#define SMEM_WORDS 16768

__global__ __launch_bounds__(256, 2) void attn_kernel(
    const float* __restrict__ x,
    const float* __restrict__ gamma,
    float* __restrict__ out)
{
    extern __shared__ unsigned su[];
    unsigned* uP = su + OP;
    float* sAl = (float*)(su + OAL);
    float* sSc = (float*)(su + OSC);

    const int t = threadIdx.x, w = t >> 5, lane = t & 31;
    const int quad = lane & 3, qr = lane >> 2;
    const int m_base = 32 * (w >> 2), o_base = 64 * (w & 3);
    const int b = blockIdx.x >> 6, q0 = (blockIdx.x & 63) * 64;
    const unsigned sbase = (unsigned)__cvta_generic_to_shared(su);

    const __half* khp = g_kh + (size_t)b * NTOK * CQ;
    const __half* klp = g_kl + (size_t)b * NTOK * CQ;
    const __half* vb  = g_vh + (size_t)b * CC * NTOK;

    // ---- Q staging (once) then hoist fragments ----
    {
        int r = t >> 2, qw = t & 3;
        size_t off = ((size_t)b * NTOK + q0 + r) * CQ + qw * 8;
        *(uint4*)(su + OQH + r * 20 + qw * 4) = *(const uint4*)(g_qh + off);
        *(uint4*)(su + OQL + r * 20 + qw * 4) = *(const uint4*)(g_ql + off);
    }

    // ---- cp.async source/dest precompute ----
    const int vc = t & 3, vrow = t >> 2;            // V: rows vrow+64r, chunk vc
    const __half* vsrc = vb + (size_t)vrow * NTOK + vc * 8;
    const int krow = (t >> 2) & 31, kc = t & 3;     // K: 128 thr hi, 128 thr lo
    const __half* ksrc = ((t < 128) ? khp : klp) + (size_t)krow * CQ + kc * 8;
    const unsigned koff0 = ((t < 128) ? OKH0 : OKL0) + krow * 20 + kc * 4;
    const unsigned koff1 = ((t < 128) ? OKH1 : OKL1) + krow * 20 + kc * 4;

    // prologue: issue tile 0 into buffer 0
    {
#pragma unroll
        for (int r = 0; r < 4; r++)
            cpa16(sbase + (OV0 + (vrow + 64 * r) * 20 + vc * 4) * 4,
                  vsrc + (size_t)(64 * r) * NTOK);
        cpa16(sbase + koff0 * 4, ksrc);
        asm volatile("cp.async.commit_group;" ::: "memory");
    }
    __syncthreads();   // Q smem visible

    // hoist Q fragments (softmax warps only)
    unsigned ah[2][4], al[2][4];
    if (w < 4) {
        const unsigned* uQh = su + OQH;
        const unsigned* uQl = su + OQL;
#pragma unroll
        for (int ks = 0; ks < 2; ks++) {
            int base = (16 * w + qr) * 20 + ks * 8 + quad;
            ah[ks][0] = uQh[base];       ah[ks][1] = uQh[base + 160];
            ah[ks][2] = uQh[base + 4];   ah[ks][3] = uQh[base + 164];
            al[ks][0] = uQl[base];       al[ks][1] = uQl[base + 160];
            al[ks][2] = uQl[base + 4];   al[ks][3] = uQl[base + 164];
        }
    }

    float4 acc[2][8];
#pragma unroll
    for (int s = 0; s < 2; s++)
#pragma unroll
        for (int o = 0; o < 8; o++) acc[s][o] = make_float4(0.f, 0.f, 0.f, 0.f);
    float run_mA = -INFINITY, run_mB = -INFINITY, run_lA = 0.f, run_lB = 0.f;

    for (int kt = 0; kt < 128; kt++) {
        const int cur = kt & 1;
        const unsigned* uKh = su + (cur ? OKH1 : OKH0);
        const unsigned* uKl = su + (cur ? OKL1 : OKL0);
        const unsigned* uV  = su + (cur ? OV1 : OV0);

        asm volatile("cp.async.wait_group 0;" ::: "memory");
        __syncthreads();   // tile kt visible; all warps done with other buffer

        if (kt + 1 < 128) {    // issue tile kt+1 into other buffer
            int jn = (kt + 1) * 32;
#pragma unroll
            for (int r = 0; r < 4; r++)
                cpa16(sbase + ((cur ? OV0 : OV1) + (vrow + 64 * r) * 20 + vc * 4) * 4,
                      vsrc + jn + (size_t)(64 * r) * NTOK);
            cpa16(sbase + (cur ? koff0 : koff1) * 4, ksrc + (size_t)jn * CQ);
            asm volatile("cp.async.commit_group;" ::: "memory");
        }

        if (w < 4) {   // S + softmax for rows 16w..16w+15
            float4 sreg[4];
#pragma unroll
            for (int nt = 0; nt < 4; nt++) {
                float4 c = make_float4(0.f, 0.f, 0.f, 0.f);
#pragma unroll
                for (int ks = 0; ks < 2; ks++) {
                    int kb = (nt * 8 + qr) * 20 + ks * 8 + quad;
                    unsigned bh0 = uKh[kb], bh1 = uKh[kb + 4];
                    unsigned bl0 = uKl[kb], bl1 = uKl[kb + 4];
                    mma16(c, ah[ks], bh0, bh1);
                    mma16(c, al[ks], bh0, bh1);
                    mma16(c, ah[ks], bl0, bl1);
                }
                sreg[nt] = c;
            }
            float mA = -INFINITY, mB = -INFINITY;
#pragma unroll
            for (int nt = 0; nt < 4; nt++) {
                mA = fmaxf(mA, fmaxf(sreg[nt].x, sreg[nt].y));
                mB = fmaxf(mB, fmaxf(sreg[nt].z, sreg[nt].w));
            }
            mA = fmaxf(mA, __shfl_xor_sync(0xffffffffu, mA, 1));
            mA = fmaxf(mA, __shfl_xor_sync(0xffffffffu, mA, 2));
            mB = fmaxf(mB, __shfl_xor_sync(0xffffffffu, mB, 1));
            mB = fmaxf(mB, __shfl_xor_sync(0xffffffffu, mB, 2));
            float mAn = fmaxf(run_mA, mA), mBn = fmaxf(run_mB, mB);
            float alA = __expf(run_mA - mAn), alB = __expf(run_mB - mBn);
            run_mA = mAn; run_mB = mBn;
            float sA = 0.f, sB = 0.f;
#pragma unroll
            for (int nt = 0; nt < 4; nt++) {
                float px = __expf(sreg[nt].x - mAn), py = __expf(sreg[nt].y - mAn);
                float pz = __expf(sreg[nt].z - mBn), pw = __expf(sreg[nt].w - mBn);
                sA += px + py; sB += pz + pw;
                __half2 hA = __floats2half2_rn(px, py);
                __half2 hB = __floats2half2_rn(pz, pw);
                uP[(16 * w + qr) * 20 + nt * 4 + quad]     = *(unsigned*)&hA;
                uP[(16 * w + qr + 8) * 20 + nt * 4 + quad] = *(unsigned*)&hB;
            }
            sA += __shfl_xor_sync(0xffffffffu, sA, 1);
            sA += __shfl_xor_sync(0xffffffffu, sA, 2);
            sB += __shfl_xor_sync(0xffffffffu, sB, 1);
            sB += __shfl_xor_sync(0xffffffffu, sB, 2);
            run_lA = run_lA * alA + sA;
            run_lB = run_lB * alB + sB;
            if (quad == 0) { sAl[16 * w + qr] = alA; sAl[16 * w + qr + 8] = alB; }
        }
        __syncthreads();   // P + alphas ready

        // rescale + PV (fp16, m16n8k16)
        float aA0 = sAl[m_base + qr],      aB0 = sAl[m_base + qr + 8];
        float aA1 = sAl[m_base + 16 + qr], aB1 = sAl[m_base + 16 + qr + 8];
#pragma unroll
        for (int o = 0; o < 8; o++) {
            acc[0][o].x *= aA0; acc[0][o].y *= aA0; acc[0][o].z *= aB0; acc[0][o].w *= aB0;
            acc[1][o].x *= aA1; acc[1][o].y *= aA1; acc[1][o].z *= aB1; acc[1][o].w *= aB1;
        }
#pragma unroll
        for (int ks = 0; ks < 2; ks++) {
            unsigned p0[4], p1[4];
            int a0i = (m_base + qr) * 20 + ks * 8 + quad;
            p0[0] = uP[a0i];     p0[1] = uP[a0i + 160];
            p0[2] = uP[a0i + 4]; p0[3] = uP[a0i + 164];
            int a1i = (m_base + 16 + qr) * 20 + ks * 8 + quad;
            p1[0] = uP[a1i];     p1[1] = uP[a1i + 160];
            p1[2] = uP[a1i + 4]; p1[3] = uP[a1i + 164];
#pragma unroll
            for (int ot = 0; ot < 8; ot++) {
                int vi = (o_base + ot * 8 + qr) * 20 + ks * 8 + quad;
                unsigned v0 = uV[vi], v1 = uV[vi + 4];
                mma16(acc[0][ot], p0, v0, v1);
                mma16(acc[1][ot], p1, v0, v1);
            }
        }
    }

    __syncthreads();
    if (w < 4 && quad == 0) {
        float gm = gamma[0];
        sSc[16 * w + qr]     = gm / run_lA;
        sSc[16 * w + qr + 8] = gm / run_lB;
    }
    __syncthreads();

    const float* xb = x   + (size_t)b * CC * NTOK;
    float*       ob = out + (size_t)b * CC * NTOK;
#pragma unroll
    for (int s = 0; s < 2; s++) {
        float scA = sSc[m_base + 16 * s + qr], scB = sSc[m_base + 16 * s + qr + 8];
        int m = q0 + m_base + 16 * s + qr;
#pragma unroll
        for (int ot = 0; ot < 8; ot++) {
            int o = o_base + ot * 8 + 2 * quad;
            float4 c = acc[s][ot];
            size_t i00 = (size_t)o * NTOK + m;
            size_t i10 = (size_t)(o + 1) * NTOK + m;
            ob[i00]     = fmaf(scA, c.x, xb[i00]);
            ob[i10]     = fmaf(scA, c.y, xb[i10]);
            ob[i00 + 8] = fmaf(scB, c.z, xb[i00 + 8]);
            ob[i10 + 8] = fmaf(scB, c.w, xb[i10 + 8]);
        }
    }
}

// ============ launch ============
extern "C" void kernel_launch(void* const* d_in, const int* in_sizes, int n_in,
                              void* d_out, int out_size)
{
    const float* x     = (const float*)d_in[0];
    const float* wq    = (const float*)d_in[1];
    const float* bq    = (const float*)d_in[2];
    const float* wk    = (const float*)d_in[3];
    const float* bk    = (const float*)d_in[4];
    const float* wv    = (const float*)d_in[5];
    const float* bv    = (const float*)d_in[6];
    const float* gamma = (const float*)d_in[7];
    float* out = (float*)d_out;

    dim3 pgrid(NTOK / 128, 5, BATCH);
    proj_kernel<<<pgrid, 256>>>(x, wq, bq, wk, bk, wv, bv);

    const int smem_bytes = SMEM_WORDS * 4;   // 67072
    cudaFuncSetAttribute(attn_kernel, cudaFuncAttributeMaxDynamicSharedMemorySize, smem_bytes);
    attn_kernel<<<BATCH * (NTOK / 64), 256, smem_bytes>>>(x, gamma, out);
}